// round 10
// baseline (speedup 1.0000x reference)
#include <cuda_runtime.h>
#include <math.h>

// Problem constants
#define NTHREADS 512
#define BATCH    128
#define TLEN     129
#define NSTEP    128   // TLEN-1
#define NWIN     16    // (TLEN-1)/8
#define OUTN     32

// ---- shared memory layout (float offsets) ----
// Only V2 rows 128..191 stay in SMEM (oct split-K layout):
//   V2o[i][tid] (4x512 float4): tid=8r'+o -> V2[128+r'][(8i+o)*4 ..]
// V0 / V1 / V2 rows 0..127 live in per-thread registers (packed f32x2),
// quad split: tid=4r+q -> K float4 indices {4i+q}.
#define OFF_V2O  0        // 8192
#define OFF_R    8192     // 2048  (R row-major 32x64)
#define OFF_RB   10240    // 32
#define OFF_C0   10272    // 128
#define OFF_C1   10400    // 128
#define OFF_C2   10528    // 192
#define OFF_Y    10720    // 64
#define OFF_Y2   10784    // 64
#define OFF_S0   10848    // 128
#define OFF_G0   10976    // 128
#define OFF_S1   11104    // 128
#define OFF_G1   11232    // 128
#define OFF_M    11360    // 192
#define OFF_TZ   11552    // 192
#define OFF_TN0  11744    // 3*128
#define OFF_TN1  12128    // 3*128
#define OFF_J    12512    // 3*192
#define OFF_SLP  13088    // 16*8 (6 used per window)
#define OFF_DTS  13216    // 128
#define SMEM_FLOATS 13344
#define SMEM_BYTES  (SMEM_FLOATS * 4)

typedef unsigned long long u64;

__device__ __forceinline__ float softplusf(float x) {
    // jax.nn.softplus == max(x,0) + log1p(exp(-|x|))
    return fmaxf(x, 0.0f) + log1pf(expf(-fabsf(x)));
}
__device__ __forceinline__ float sigmoidf_(float x) {
    return 1.0f / (1.0f + expf(-x));
}

// packed f32x2 fma: lanewise d = a*b + c
__device__ __forceinline__ u64 ffma2(u64 a, u64 b, u64 c) {
    u64 d;
    asm("fma.rn.f32x2 %0, %1, %2, %3;" : "=l"(d) : "l"(a), "l"(b), "l"(c));
    return d;
}
__device__ __forceinline__ u64 fadd2(u64 a, u64 b) {
    u64 d;
    asm("add.rn.f32x2 %0, %1, %2;" : "=l"(d) : "l"(a), "l"(b));
    return d;
}
// horizontal add of the two f32 lanes
__device__ __forceinline__ float hadd2(u64 v) {
    unsigned lo, hi;
    asm("mov.b64 {%0, %1}, %2;" : "=r"(lo), "=r"(hi) : "l"(v));
    return __uint_as_float(lo) + __uint_as_float(hi);
}
// LDS.128 into two packed f32x2 (64-bit register pairs)
__device__ __forceinline__ void lds_v2u64(const float* p, u64& a, u64& b) {
    unsigned addr = (unsigned)__cvta_generic_to_shared(p);
    asm volatile("ld.shared.v2.u64 {%0, %1}, [%2];" : "=l"(a), "=l"(b) : "r"(addr));
}

// quad reduce (4 consecutive lanes)
__device__ __forceinline__ float qred(float s) {
    s += __shfl_xor_sync(0xffffffffu, s, 1);
    s += __shfl_xor_sync(0xffffffffu, s, 2);
    return s;
}
// oct reduce (8 consecutive lanes)
__device__ __forceinline__ float ored(float s) {
    s += __shfl_xor_sync(0xffffffffu, s, 1);
    s += __shfl_xor_sync(0xffffffffu, s, 2);
    s += __shfl_xor_sync(0xffffffffu, s, 4);
    return s;
}

// F(y) . s. 512 threads, quad/oct split-K, register-resident weights.
// Returns k[tid] in a register (valid for tid<64).
__device__ __forceinline__ float eval_F(float* sm, int tid,
                                        const float* __restrict__ yin,
                                        const float* __restrict__ svec,
                                        const u64* __restrict__ w0p,   // 8  (V0 row rq, quad slice)
                                        const u64* __restrict__ w1p,   // 16 (V1 row rq, quad slice)
                                        const u64* __restrict__ w2p)   // 16 (V2 row rq, quad slice)
{
    const int rq = tid >> 2, q = tid & 3;    // quad mapping (128 rows x 4)
    const int ro = tid >> 3, o = tid & 7;    // oct mapping  (64 rows x 8)
    float* s0  = sm + OFF_S0;  float* g0 = sm + OFF_G0;
    float* s1  = sm + OFF_S1;  float* g1 = sm + OFF_G1;
    float* msm = sm + OFF_M;   float* tz = sm + OFF_TZ;
    float* tn0 = sm + OFF_TN0; float* tn1 = sm + OFF_TN1;
    float* J   = sm + OFF_J;
    const float* V2o = sm + OFF_V2O;

    // ---------- forward layer 0: u0 = V0 @ y + c0 (K=64, 4 iters) ----------
    {
        u64 acc0 = 0ull, acc1 = 0ull;
#pragma unroll
        for (int i = 0; i < 4; i++) {
            u64 a0, a1;
            lds_v2u64(yin + (4 * i + q) * 4, a0, a1);
            acc0 = ffma2(w0p[2 * i], a0, acc0);
            acc1 = ffma2(w0p[2 * i + 1], a1, acc1);
        }
        float s = qred(hadd2(fadd2(acc0, acc1)));
        if (q == 0) {
            float u = sm[OFF_C0 + rq] + s;
            s0[rq] = softplusf(u);
            g0[rq] = sigmoidf_(u);
        }
    }
    __syncthreads();
    // ---------- forward layer 1 (K=128, 8 iters) ----------
    {
        u64 acc0 = 0ull, acc1 = 0ull;
#pragma unroll
        for (int i = 0; i < 8; i++) {
            u64 a0, a1;
            lds_v2u64(s0 + (4 * i + q) * 4, a0, a1);
            acc0 = ffma2(w1p[2 * i], a0, acc0);
            acc1 = ffma2(w1p[2 * i + 1], a1, acc1);
        }
        float s = qred(hadd2(fadd2(acc0, acc1)));
        if (q == 0) {
            float u = sm[OFF_C1 + rq] + s;
            s1[rq] = softplusf(u);
            g1[rq] = sigmoidf_(u);
        }
    }
    __syncthreads();
    // ---------- forward layer 2 (192 rows) ----------
    {
        {   // rows 0..127 (quads, register weights)
            u64 acc0 = 0ull, acc1 = 0ull;
#pragma unroll
            for (int i = 0; i < 8; i++) {
                u64 a0, a1;
                lds_v2u64(s1 + (4 * i + q) * 4, a0, a1);
                acc0 = ffma2(w2p[2 * i], a0, acc0);
                acc1 = ffma2(w2p[2 * i + 1], a1, acc1);
            }
            float s = qred(hadd2(fadd2(acc0, acc1)));
            if (q == 0) {
                float z = sm[OFF_C2 + rq] + s;
                float m = tanhf(z);
                msm[rq] = m; tz[rq] = 1.0f - m * m;
            }
        }
        {   // rows 128..191 (octs, SMEM weights)
            u64 acc0 = 0ull, acc1 = 0ull;
#pragma unroll
            for (int i = 0; i < 4; i++) {
                u64 w0, w1, a0, a1;
                lds_v2u64(V2o + (i * 512 + tid) * 4, w0, w1);
                lds_v2u64(s1 + (8 * i + o) * 4, a0, a1);
                acc0 = ffma2(w0, a0, acc0);
                acc1 = ffma2(w1, a1, acc1);
            }
            float s = ored(hadd2(fadd2(acc0, acc1)));
            if (o == 0) {
                int r = 128 + ro;
                float z = sm[OFF_C2 + r] + s;
                float m = tanhf(z);
                msm[r] = m; tz[r] = 1.0f - m * m;
            }
        }
    }
    __syncthreads();
    // ---------- JVP layer 0 (3 tangents = rows of m; K=64, 4 iters) ----------
    {
        u64 d0 = 0ull, d1 = 0ull, d2 = 0ull;
#pragma unroll
        for (int i = 0; i < 4; i++) {
            u64 a0, a1, b0, b1, c0v, c1v;
            lds_v2u64(msm + (4 * i + q) * 4, a0, a1);
            lds_v2u64(msm + 64 + (4 * i + q) * 4, b0, b1);
            lds_v2u64(msm + 128 + (4 * i + q) * 4, c0v, c1v);
            u64 wa = w0p[2 * i], wb = w0p[2 * i + 1];
            d0 = ffma2(wa, a0, d0);  d0 = ffma2(wb, a1, d0);
            d1 = ffma2(wa, b0, d1);  d1 = ffma2(wb, b1, d1);
            d2 = ffma2(wa, c0v, d2); d2 = ffma2(wb, c1v, d2);
        }
        float e0 = qred(hadd2(d0));
        float e1 = qred(hadd2(d1));
        float e2 = qred(hadd2(d2));
        if (q == 0) {
            float g = g0[rq];
            tn0[rq]       = g * e0;
            tn0[128 + rq] = g * e1;
            tn0[256 + rq] = g * e2;
        }
    }
    __syncthreads();
    // ---------- JVP layer 1 (K=128, 8 iters) ----------
    {
        u64 d0 = 0ull, d1 = 0ull, d2 = 0ull;
#pragma unroll
        for (int i = 0; i < 8; i++) {
            u64 a0, a1, b0, b1, c0v, c1v;
            lds_v2u64(tn0 + (4 * i + q) * 4, a0, a1);
            lds_v2u64(tn0 + 128 + (4 * i + q) * 4, b0, b1);
            lds_v2u64(tn0 + 256 + (4 * i + q) * 4, c0v, c1v);
            u64 wa = w1p[2 * i], wb = w1p[2 * i + 1];
            d0 = ffma2(wa, a0, d0);  d0 = ffma2(wb, a1, d0);
            d1 = ffma2(wa, b0, d1);  d1 = ffma2(wb, b1, d1);
            d2 = ffma2(wa, c0v, d2); d2 = ffma2(wb, c1v, d2);
        }
        float e0 = qred(hadd2(d0));
        float e1 = qred(hadd2(d1));
        float e2 = qred(hadd2(d2));
        if (q == 0) {
            float g = g1[rq];
            tn1[rq]       = g * e0;
            tn1[128 + rq] = g * e1;
            tn1[256 + rq] = g * e2;
        }
    }
    __syncthreads();
    // ---------- JVP layer 2 ----------
    {
        {   // rows 0..127 (quads, register weights)
            u64 d0 = 0ull, d1 = 0ull, d2 = 0ull;
#pragma unroll
            for (int i = 0; i < 8; i++) {
                u64 a0, a1, b0, b1, c0v, c1v;
                lds_v2u64(tn1 + (4 * i + q) * 4, a0, a1);
                lds_v2u64(tn1 + 128 + (4 * i + q) * 4, b0, b1);
                lds_v2u64(tn1 + 256 + (4 * i + q) * 4, c0v, c1v);
                u64 wa = w2p[2 * i], wb = w2p[2 * i + 1];
                d0 = ffma2(wa, a0, d0);  d0 = ffma2(wb, a1, d0);
                d1 = ffma2(wa, b0, d1);  d1 = ffma2(wb, b1, d1);
                d2 = ffma2(wa, c0v, d2); d2 = ffma2(wb, c1v, d2);
            }
            float e0 = qred(hadd2(d0));
            float e1 = qred(hadd2(d1));
            float e2 = qred(hadd2(d2));
            if (q == 0) {
                float tzv = tz[rq];
                J[rq]       = tzv * e0;
                J[192 + rq] = tzv * e1;
                J[384 + rq] = tzv * e2;
            }
        }
        {   // rows 128..191 (octs, SMEM weights)
            u64 d0 = 0ull, d1 = 0ull, d2 = 0ull;
#pragma unroll
            for (int i = 0; i < 4; i++) {
                u64 w0, w1, a0, a1, b0, b1, c0v, c1v;
                lds_v2u64(V2o + (i * 512 + tid) * 4, w0, w1);
                lds_v2u64(tn1 + (8 * i + o) * 4, a0, a1);
                lds_v2u64(tn1 + 128 + (8 * i + o) * 4, b0, b1);
                lds_v2u64(tn1 + 256 + (8 * i + o) * 4, c0v, c1v);
                d0 = ffma2(w0, a0, d0);  d0 = ffma2(w1, a1, d0);
                d1 = ffma2(w0, b0, d1);  d1 = ffma2(w1, b1, d1);
                d2 = ffma2(w0, c0v, d2); d2 = ffma2(w1, c1v, d2);
            }
            float e0 = ored(hadd2(d0));
            float e1 = ored(hadd2(d1));
            float e2 = ored(hadd2(d2));
            if (o == 0) {
                int r = 128 + ro;
                float tzv = tz[r];
                J[r]       = tzv * e0;
                J[192 + r] = tzv * e1;
                J[384 + r] = tzv * e2;
            }
        }
    }
    __syncthreads();
    // ---------- combine: k[h] = m.T s[0:3] + br.T s[3:6] ----------
    float k = 0.f;
    if (tid < 64) {
        k =  msm[tid]        * svec[0]
           + msm[64 + tid]   * svec[1]
           + msm[128 + tid]  * svec[2]
           + (J[64 + tid]  - J[192 + tid]) * svec[3]
           + (J[128 + tid] - J[384 + tid]) * svec[4]
           + (J[320 + tid] - J[448 + tid]) * svec[5];
    }
    return k;
}

// Output projection: out_row[o] = tanh(dot(y, R[o,:]) + rb[o])
// 512 threads: 16 threads per output, 4-dim partials, shuffle-reduce.
__device__ __forceinline__ void write_out_row(const float* sm, int t, float* __restrict__ dst)
{
    int ot = t >> 4, part = t & 15;
    const float* r = sm + OFF_R + ot * 64 + part * 4;
    const float* y = sm + OFF_Y + part * 4;
    float s = 0.f;
#pragma unroll
    for (int j = 0; j < 4; j++) s = fmaf(r[j], y[j], s);
    s += __shfl_xor_sync(0xffffffffu, s, 1);
    s += __shfl_xor_sync(0xffffffffu, s, 2);
    s += __shfl_xor_sync(0xffffffffu, s, 4);
    s += __shfl_xor_sync(0xffffffffu, s, 8);
    if (part == 0) dst[ot] = tanhf(s + sm[OFF_RB + ot]);
}

__global__ void __launch_bounds__(NTHREADS, 1)
ncde_kernel(const float* __restrict__ ts, const float* __restrict__ x,
            const float* __restrict__ W0, const float* __restrict__ b0,
            const float* __restrict__ W1, const float* __restrict__ b1,
            const float* __restrict__ W2, const float* __restrict__ b2,
            const float* __restrict__ V0, const float* __restrict__ c0,
            const float* __restrict__ V1, const float* __restrict__ c1,
            const float* __restrict__ V2, const float* __restrict__ c2,
            const float* __restrict__ R,  const float* __restrict__ rb,
            float* __restrict__ out)
{
    extern __shared__ float sm[];
    const int t = threadIdx.x;
    const int b = blockIdx.x;
    const int rq = t >> 2, q = t & 3;

    // ---- pin per-thread quad weight slices in registers (packed f32x2) ----
    u64 w0p[8], w1p[16], w2p[16];
#pragma unroll
    for (int i = 0; i < 4; i++) {
        ulonglong2 v = *(const ulonglong2*)(V0 + rq * 64 + (4 * i + q) * 4);
        w0p[2 * i] = v.x; w0p[2 * i + 1] = v.y;
    }
#pragma unroll
    for (int i = 0; i < 8; i++) {
        ulonglong2 v = *(const ulonglong2*)(V1 + rq * 128 + (4 * i + q) * 4);
        w1p[2 * i] = v.x; w1p[2 * i + 1] = v.y;
    }
#pragma unroll
    for (int i = 0; i < 8; i++) {
        ulonglong2 v = *(const ulonglong2*)(V2 + rq * 128 + (4 * i + q) * 4);
        w2p[2 * i] = v.x; w2p[2 * i + 1] = v.y;
    }

    // ---- stage V2 rows 128..191 into SMEM (oct split-K layout) ----
    for (int idx = t; idx < 4 * 512; idx += NTHREADS) {
        int i = idx >> 9, tt = idx & 511;
        int ro = tt >> 3, o = tt & 7;
        ((float4*)(sm + OFF_V2O))[idx] = *(const float4*)(V2 + (128 + ro) * 128 + (8 * i + o) * 4);
    }
    for (int i = t; i < 2048; i += NTHREADS) sm[OFF_R + i] = R[i];
    if (t < 32) sm[OFF_RB + t] = rb[t];
    if (t < 128) { sm[OFF_C0 + t] = c0[t]; sm[OFF_C1 + t] = c1[t]; }
    if (t < 192) sm[OFF_C2 + t] = c2[t];

    // ---- per-batch: dt array ----
    {
        const float* tsb = ts + b * TLEN;
        for (int i = t; i < NSTEP; i += NTHREADS) sm[OFF_DTS + i] = tsb[i + 1] - tsb[i];
    }

    // ---- per-batch: window log-signature slopes (16 windows x 6 channels) ----
    if (t < NWIN) {
        const float* xp = x + (b * TLEN + t * 8) * 3;
        float p[9][3];
#pragma unroll
        for (int k = 0; k < 9; k++) {
            p[k][0] = xp[k * 3 + 0];
            p[k][1] = xp[k * 3 + 1];
            p[k][2] = xp[k * 3 + 2];
        }
        float a01 = 0.f, a10 = 0.f, a02 = 0.f, a20 = 0.f, a12 = 0.f, a21 = 0.f;
#pragma unroll
        for (int k = 0; k < 8; k++) {
            float r0 = p[k][0] - p[0][0], r1 = p[k][1] - p[0][1], r2 = p[k][2] - p[0][2];
            float d0 = p[k + 1][0] - p[k][0], d1 = p[k + 1][1] - p[k][1], d2 = p[k + 1][2] - p[k][2];
            a01 = fmaf(r0, d1, a01); a10 = fmaf(r1, d0, a10);
            a02 = fmaf(r0, d2, a02); a20 = fmaf(r2, d0, a20);
            a12 = fmaf(r1, d2, a12); a21 = fmaf(r2, d1, a21);
        }
        const float* tsb = ts + b * TLEN;
        float td = tsb[(t + 1) * 8] - tsb[t * 8];
        float* sl = sm + OFF_SLP + t * 8;
        sl[0] = (p[8][0] - p[0][0]) / td;
        sl[1] = (p[8][1] - p[0][1]) / td;
        sl[2] = (p[8][2] - p[0][2]) / td;
        sl[3] = (0.5f * (a01 - a10)) / td;
        sl[4] = (0.5f * (a02 - a20)) / td;
        sl[5] = (0.5f * (a12 - a21)) / td;
    }
    __syncthreads();

    // ---- init MLP: h0 = W2 @ sp(W1 @ sp(W0 @ x0 + b0) + b1) + b2 ----
    if (t < 128) {
        const float* xp = x + b * TLEN * 3;
        float x0 = xp[0], x1 = xp[1], x2 = xp[2];
        float u = b0[t] + W0[t * 3] * x0 + W0[t * 3 + 1] * x1 + W0[t * 3 + 2] * x2;
        sm[OFF_S0 + t] = softplusf(u);
    }
    __syncthreads();
    if (t < 128) {
        float acc = b1[t];
        const float* w = W1 + t * 128;
#pragma unroll 4
        for (int j = 0; j < 128; j++) acc = fmaf(w[j], sm[OFF_S0 + j], acc);
        sm[OFF_S1 + t] = softplusf(acc);
    }
    __syncthreads();
    if (t < 64) {
        float acc = b2[t];
        const float* w = W2 + t * 128;
#pragma unroll 4
        for (int j = 0; j < 128; j++) acc = fmaf(w[j], sm[OFF_S1 + j], acc);
        sm[OFF_Y + t] = acc;
    }
    __syncthreads();

    // ---- output row 0 (from h0) ----
    write_out_row(sm, t, out + (b * TLEN + 0) * OUTN);

    // ---- RK2 (Heun) scan over 128 steps ----
    for (int i = 0; i < NSTEP; i++) {
        float dt = sm[OFF_DTS + i];
        const float* svec = sm + OFF_SLP + ((i >> 3) << 3);

        float k1 = eval_F(sm, t, sm + OFF_Y, svec, w0p, w1p, w2p);
        if (t < 64) sm[OFF_Y2 + t] = sm[OFF_Y + t] + dt * k1;
        __syncthreads();

        float k2 = eval_F(sm, t, sm + OFF_Y2, svec, w0p, w1p, w2p);
        if (t < 64) sm[OFF_Y + t] += 0.5f * dt * (k1 + k2);
        __syncthreads();

        write_out_row(sm, t, out + (b * TLEN + i + 1) * OUTN);
    }
}

extern "C" void kernel_launch(void* const* d_in, const int* in_sizes, int n_in,
                              void* d_out, int out_size)
{
    const float* ts = (const float*)d_in[0];
    const float* x  = (const float*)d_in[1];
    const float* W0 = (const float*)d_in[2];
    const float* b0 = (const float*)d_in[3];
    const float* W1 = (const float*)d_in[4];
    const float* b1 = (const float*)d_in[5];
    const float* W2 = (const float*)d_in[6];
    const float* b2 = (const float*)d_in[7];
    const float* V0 = (const float*)d_in[8];
    const float* c0 = (const float*)d_in[9];
    const float* V1 = (const float*)d_in[10];
    const float* c1 = (const float*)d_in[11];
    const float* V2 = (const float*)d_in[12];
    const float* c2 = (const float*)d_in[13];
    const float* R  = (const float*)d_in[14];
    const float* rb = (const float*)d_in[15];
    float* out = (float*)d_out;

    cudaFuncSetAttribute(ncde_kernel, cudaFuncAttributeMaxDynamicSharedMemorySize, SMEM_BYTES);
    ncde_kernel<<<BATCH, NTHREADS, SMEM_BYTES>>>(ts, x, W0, b0, W1, b1, W2, b2,
                                                 V0, c0, V1, c1, V2, c2, R, rb, out);
}

// round 11
// speedup vs baseline: 1.7647x; 1.7647x over previous
#include <cuda_runtime.h>
#include <math.h>

// Problem constants
#define NTHREADS 256
#define BATCH    128
#define TLEN     129
#define NSTEP    128   // TLEN-1
#define NWIN     16    // (TLEN-1)/8
#define OUTN     32

// ---- shared memory layout (float offsets) ----
// ALL weights live in per-thread registers (packed f32x2).
// Thread t = 4r+q (r<64,q<4) owns rows {r, r+64} of V0/V1/V2[0:128],
// row 128+r of V2[128:192], K-quarter q (float4 indices 4i+q).
#define OFF_R    0        // 2048  (R row-major 32x64)
#define OFF_RB   2048     // 32
#define OFF_C0   2080     // 128
#define OFF_C1   2208     // 128
#define OFF_C2   2336     // 192
#define OFF_Y    2528     // 64
#define OFF_Y2   2592     // 64
#define OFF_S0   2656     // 128
#define OFF_S1   2784     // 128
#define OFF_M    2912     // 192
#define OFF_TN0  3104     // 3*128
#define OFF_TN1  3488     // 3*128
#define OFF_J    3872     // 3*192
#define OFF_SLP  4448     // 16*8 (6 used per window)
#define OFF_DTS  4576     // 128
#define SMEM_FLOATS 4704
#define SMEM_BYTES  (SMEM_FLOATS * 4)

typedef unsigned long long u64;

__device__ __forceinline__ float softplusf(float x) {
    // jax.nn.softplus == max(x,0) + log1p(exp(-|x|))
    return fmaxf(x, 0.0f) + log1pf(expf(-fabsf(x)));
}
__device__ __forceinline__ float sigmoidf_(float x) {
    return 1.0f / (1.0f + expf(-x));
}

// packed f32x2 fma: lanewise d = a*b + c
__device__ __forceinline__ u64 ffma2(u64 a, u64 b, u64 c) {
    u64 d;
    asm("fma.rn.f32x2 %0, %1, %2, %3;" : "=l"(d) : "l"(a), "l"(b), "l"(c));
    return d;
}
// horizontal add of the two f32 lanes
__device__ __forceinline__ float hadd2(u64 v) {
    unsigned lo, hi;
    asm("mov.b64 {%0, %1}, %2;" : "=r"(lo), "=r"(hi) : "l"(v));
    return __uint_as_float(lo) + __uint_as_float(hi);
}
// LDS.128 into two packed f32x2 (64-bit register pairs)
__device__ __forceinline__ void lds_v2u64(const float* p, u64& a, u64& b) {
    unsigned addr = (unsigned)__cvta_generic_to_shared(p);
    asm volatile("ld.shared.v2.u64 {%0, %1}, [%2];" : "=l"(a), "=l"(b) : "r"(addr));
}
// butterfly reduce over 4 consecutive lanes (result valid in ALL lanes)
__device__ __forceinline__ float qred(float s) {
    s += __shfl_xor_sync(0xffffffffu, s, 1);
    s += __shfl_xor_sync(0xffffffffu, s, 2);
    return s;
}

// Persistent per-thread state for eval_F (register-resident weights + gate regs)
struct FState {
    u64 w0[16];   // V0 rows r,r+64   : [row01*8  + 2i + j], i<4
    u64 w1[32];   // V1 rows r,r+64   : [row01*16 + 2i + j], i<8
    u64 w2a[32];  // V2 rows r,r+64   : [row01*16 + 2i + j], i<8
    u64 w2b[16];  // V2 row 128+r     : [2i + j], i<8
};

// F(y) . s. 256 threads, row-pair x quarter-K split, all weights in registers.
// Returns k[tid] (valid for tid<64).
__device__ __forceinline__ float eval_F(float* sm, int tid,
                                        const float* __restrict__ yin,
                                        const float* __restrict__ svec,
                                        const FState& W)
{
    const int r = tid >> 2, q = tid & 3;
    float* s0  = sm + OFF_S0;
    float* s1  = sm + OFF_S1;
    float* msm = sm + OFF_M;
    float* tn0 = sm + OFF_TN0;
    float* tn1 = sm + OFF_TN1;
    float* J   = sm + OFF_J;

    float g0a, g0b, g1a, g1b, tza, tzb, tzc;   // gates kept in registers (valid all lanes)

    // ---------- forward layer 0: u0 = V0 @ y + c0 (K=64) ----------
    {
        u64 acc0 = 0ull, acc1 = 0ull;
#pragma unroll
        for (int i = 0; i < 4; i++) {
            u64 a0, a1;
            lds_v2u64(yin + (4 * i + q) * 4, a0, a1);
            acc0 = ffma2(W.w0[2 * i], a0, acc0);
            acc0 = ffma2(W.w0[2 * i + 1], a1, acc0);
            acc1 = ffma2(W.w0[8 + 2 * i], a0, acc1);
            acc1 = ffma2(W.w0[8 + 2 * i + 1], a1, acc1);
        }
        float sa = qred(hadd2(acc0));
        float sb = qred(hadd2(acc1));
        float ua = sm[OFF_C0 + r] + sa;
        float ub = sm[OFF_C0 + r + 64] + sb;
        g0a = sigmoidf_(ua); g0b = sigmoidf_(ub);
        if (q == 0) {
            s0[r]      = softplusf(ua);
            s0[r + 64] = softplusf(ub);
        }
    }
    __syncthreads();
    // ---------- forward layer 1 (K=128) ----------
    {
        u64 acc0 = 0ull, acc1 = 0ull;
#pragma unroll
        for (int i = 0; i < 8; i++) {
            u64 a0, a1;
            lds_v2u64(s0 + (4 * i + q) * 4, a0, a1);
            acc0 = ffma2(W.w1[2 * i], a0, acc0);
            acc0 = ffma2(W.w1[2 * i + 1], a1, acc0);
            acc1 = ffma2(W.w1[16 + 2 * i], a0, acc1);
            acc1 = ffma2(W.w1[16 + 2 * i + 1], a1, acc1);
        }
        float sa = qred(hadd2(acc0));
        float sb = qred(hadd2(acc1));
        float ua = sm[OFF_C1 + r] + sa;
        float ub = sm[OFF_C1 + r + 64] + sb;
        g1a = sigmoidf_(ua); g1b = sigmoidf_(ub);
        if (q == 0) {
            s1[r]      = softplusf(ua);
            s1[r + 64] = softplusf(ub);
        }
    }
    __syncthreads();
    // ---------- forward layer 2 (192 rows: r, r+64, 128+r) ----------
    {
        u64 acc0 = 0ull, acc1 = 0ull, acc2 = 0ull;
#pragma unroll
        for (int i = 0; i < 8; i++) {
            u64 a0, a1;
            lds_v2u64(s1 + (4 * i + q) * 4, a0, a1);
            acc0 = ffma2(W.w2a[2 * i], a0, acc0);
            acc0 = ffma2(W.w2a[2 * i + 1], a1, acc0);
            acc1 = ffma2(W.w2a[16 + 2 * i], a0, acc1);
            acc1 = ffma2(W.w2a[16 + 2 * i + 1], a1, acc1);
            acc2 = ffma2(W.w2b[2 * i], a0, acc2);
            acc2 = ffma2(W.w2b[2 * i + 1], a1, acc2);
        }
        float sa = qred(hadd2(acc0));
        float sb = qred(hadd2(acc1));
        float sc = qred(hadd2(acc2));
        float ma = tanhf(sm[OFF_C2 + r] + sa);
        float mb = tanhf(sm[OFF_C2 + r + 64] + sb);
        float mc = tanhf(sm[OFF_C2 + 128 + r] + sc);
        tza = 1.0f - ma * ma; tzb = 1.0f - mb * mb; tzc = 1.0f - mc * mc;
        if (q == 0) {
            msm[r] = ma; msm[r + 64] = mb; msm[128 + r] = mc;
        }
    }
    __syncthreads();
    // ---------- JVP layer 0 (3 tangents = rows of m; K=64) ----------
    {
        u64 d00 = 0ull, d01 = 0ull, d02 = 0ull;
        u64 d10 = 0ull, d11 = 0ull, d12 = 0ull;
#pragma unroll
        for (int i = 0; i < 4; i++) {
            u64 a0, a1, b0, b1, c0v, c1v;
            lds_v2u64(msm + (4 * i + q) * 4, a0, a1);
            lds_v2u64(msm + 64 + (4 * i + q) * 4, b0, b1);
            lds_v2u64(msm + 128 + (4 * i + q) * 4, c0v, c1v);
            u64 wa0 = W.w0[2 * i], wa1 = W.w0[2 * i + 1];
            u64 wb0 = W.w0[8 + 2 * i], wb1 = W.w0[8 + 2 * i + 1];
            d00 = ffma2(wa0, a0, d00);  d00 = ffma2(wa1, a1, d00);
            d01 = ffma2(wa0, b0, d01);  d01 = ffma2(wa1, b1, d01);
            d02 = ffma2(wa0, c0v, d02); d02 = ffma2(wa1, c1v, d02);
            d10 = ffma2(wb0, a0, d10);  d10 = ffma2(wb1, a1, d10);
            d11 = ffma2(wb0, b0, d11);  d11 = ffma2(wb1, b1, d11);
            d12 = ffma2(wb0, c0v, d12); d12 = ffma2(wb1, c1v, d12);
        }
        float e00 = qred(hadd2(d00)), e01 = qred(hadd2(d01)), e02 = qred(hadd2(d02));
        float e10 = qred(hadd2(d10)), e11 = qred(hadd2(d11)), e12 = qred(hadd2(d12));
        if (q == 0) {
            tn0[r]            = g0a * e00;
            tn0[128 + r]      = g0a * e01;
            tn0[256 + r]      = g0a * e02;
            tn0[r + 64]       = g0b * e10;
            tn0[128 + r + 64] = g0b * e11;
            tn0[256 + r + 64] = g0b * e12;
        }
    }
    __syncthreads();
    // ---------- JVP layer 1 (K=128) ----------
    {
        u64 d00 = 0ull, d01 = 0ull, d02 = 0ull;
        u64 d10 = 0ull, d11 = 0ull, d12 = 0ull;
#pragma unroll
        for (int i = 0; i < 8; i++) {
            u64 a0, a1, b0, b1, c0v, c1v;
            lds_v2u64(tn0 + (4 * i + q) * 4, a0, a1);
            lds_v2u64(tn0 + 128 + (4 * i + q) * 4, b0, b1);
            lds_v2u64(tn0 + 256 + (4 * i + q) * 4, c0v, c1v);
            u64 wa0 = W.w1[2 * i], wa1 = W.w1[2 * i + 1];
            u64 wb0 = W.w1[16 + 2 * i], wb1 = W.w1[16 + 2 * i + 1];
            d00 = ffma2(wa0, a0, d00);  d00 = ffma2(wa1, a1, d00);
            d01 = ffma2(wa0, b0, d01);  d01 = ffma2(wa1, b1, d01);
            d02 = ffma2(wa0, c0v, d02); d02 = ffma2(wa1, c1v, d02);
            d10 = ffma2(wb0, a0, d10);  d10 = ffma2(wb1, a1, d10);
            d11 = ffma2(wb0, b0, d11);  d11 = ffma2(wb1, b1, d11);
            d12 = ffma2(wb0, c0v, d12); d12 = ffma2(wb1, c1v, d12);
        }
        float e00 = qred(hadd2(d00)), e01 = qred(hadd2(d01)), e02 = qred(hadd2(d02));
        float e10 = qred(hadd2(d10)), e11 = qred(hadd2(d11)), e12 = qred(hadd2(d12));
        if (q == 0) {
            tn1[r]            = g1a * e00;
            tn1[128 + r]      = g1a * e01;
            tn1[256 + r]      = g1a * e02;
            tn1[r + 64]       = g1b * e10;
            tn1[128 + r + 64] = g1b * e11;
            tn1[256 + r + 64] = g1b * e12;
        }
    }
    __syncthreads();
    // ---------- JVP layer 2 (192 rows x 3 tangents) ----------
    {
        u64 d00 = 0ull, d01 = 0ull, d02 = 0ull;
        u64 d10 = 0ull, d11 = 0ull, d12 = 0ull;
        u64 d20 = 0ull, d21 = 0ull, d22 = 0ull;
#pragma unroll
        for (int i = 0; i < 8; i++) {
            u64 a0, a1, b0, b1, c0v, c1v;
            lds_v2u64(tn1 + (4 * i + q) * 4, a0, a1);
            lds_v2u64(tn1 + 128 + (4 * i + q) * 4, b0, b1);
            lds_v2u64(tn1 + 256 + (4 * i + q) * 4, c0v, c1v);
            u64 wa0 = W.w2a[2 * i], wa1 = W.w2a[2 * i + 1];
            u64 wb0 = W.w2a[16 + 2 * i], wb1 = W.w2a[16 + 2 * i + 1];
            u64 wc0 = W.w2b[2 * i], wc1 = W.w2b[2 * i + 1];
            d00 = ffma2(wa0, a0, d00);  d00 = ffma2(wa1, a1, d00);
            d01 = ffma2(wa0, b0, d01);  d01 = ffma2(wa1, b1, d01);
            d02 = ffma2(wa0, c0v, d02); d02 = ffma2(wa1, c1v, d02);
            d10 = ffma2(wb0, a0, d10);  d10 = ffma2(wb1, a1, d10);
            d11 = ffma2(wb0, b0, d11);  d11 = ffma2(wb1, b1, d11);
            d12 = ffma2(wb0, c0v, d12); d12 = ffma2(wb1, c1v, d12);
            d20 = ffma2(wc0, a0, d20);  d20 = ffma2(wc1, a1, d20);
            d21 = ffma2(wc0, b0, d21);  d21 = ffma2(wc1, b1, d21);
            d22 = ffma2(wc0, c0v, d22); d22 = ffma2(wc1, c1v, d22);
        }
        float e00 = qred(hadd2(d00)), e01 = qred(hadd2(d01)), e02 = qred(hadd2(d02));
        float e10 = qred(hadd2(d10)), e11 = qred(hadd2(d11)), e12 = qred(hadd2(d12));
        float e20 = qred(hadd2(d20)), e21 = qred(hadd2(d21)), e22 = qred(hadd2(d22));
        if (q == 0) {
            J[r]             = tza * e00;
            J[192 + r]       = tza * e01;
            J[384 + r]       = tza * e02;
            J[r + 64]        = tzb * e10;
            J[192 + r + 64]  = tzb * e11;
            J[384 + r + 64]  = tzb * e12;
            J[128 + r]       = tzc * e20;
            J[192 + 128 + r] = tzc * e21;
            J[384 + 128 + r] = tzc * e22;
        }
    }
    __syncthreads();
    // ---------- combine: k = m.T s[0:3] + br.T s[3:6] ----------
    float k = 0.f;
    if (tid < 64) {
        k =  msm[tid]        * svec[0]
           + msm[64 + tid]   * svec[1]
           + msm[128 + tid]  * svec[2]
           + (J[64 + tid]  - J[192 + tid]) * svec[3]
           + (J[128 + tid] - J[384 + tid]) * svec[4]
           + (J[320 + tid] - J[448 + tid]) * svec[5];
    }
    return k;
}

// Output projection: out_row[o] = tanh(dot(y, R[o,:]) + rb[o])
// 256 threads: 8 threads per output, 8-dim partials, shuffle-reduce.
__device__ __forceinline__ void write_out_row(const float* sm, int t, float* __restrict__ dst)
{
    int o = t >> 3, part = t & 7;
    const float* r = sm + OFF_R + o * 64 + part * 8;
    const float* y = sm + OFF_Y + part * 8;
    float s = 0.f;
#pragma unroll
    for (int j = 0; j < 8; j++) s = fmaf(r[j], y[j], s);
    s += __shfl_xor_sync(0xffffffffu, s, 1);
    s += __shfl_xor_sync(0xffffffffu, s, 2);
    s += __shfl_xor_sync(0xffffffffu, s, 4);
    if (part == 0) dst[o] = tanhf(s + sm[OFF_RB + o]);
}

__global__ void __launch_bounds__(NTHREADS, 1)
ncde_kernel(const float* __restrict__ ts, const float* __restrict__ x,
            const float* __restrict__ W0, const float* __restrict__ b0,
            const float* __restrict__ W1, const float* __restrict__ b1,
            const float* __restrict__ W2, const float* __restrict__ b2,
            const float* __restrict__ V0, const float* __restrict__ c0,
            const float* __restrict__ V1, const float* __restrict__ c1,
            const float* __restrict__ V2, const float* __restrict__ c2,
            const float* __restrict__ R,  const float* __restrict__ rb,
            float* __restrict__ out)
{
    extern __shared__ float sm[];
    const int t = threadIdx.x;
    const int b = blockIdx.x;
    const int r = t >> 2, q = t & 3;

    // ---- pin per-thread weight slices in registers (packed f32x2) ----
    FState W;
#pragma unroll
    for (int ro = 0; ro < 2; ro++) {
        int row = r + 64 * ro;
#pragma unroll
        for (int i = 0; i < 4; i++) {
            ulonglong2 v = *(const ulonglong2*)(V0 + row * 64 + (4 * i + q) * 4);
            W.w0[ro * 8 + 2 * i] = v.x; W.w0[ro * 8 + 2 * i + 1] = v.y;
        }
#pragma unroll
        for (int i = 0; i < 8; i++) {
            ulonglong2 v = *(const ulonglong2*)(V1 + row * 128 + (4 * i + q) * 4);
            W.w1[ro * 16 + 2 * i] = v.x; W.w1[ro * 16 + 2 * i + 1] = v.y;
        }
#pragma unroll
        for (int i = 0; i < 8; i++) {
            ulonglong2 v = *(const ulonglong2*)(V2 + row * 128 + (4 * i + q) * 4);
            W.w2a[ro * 16 + 2 * i] = v.x; W.w2a[ro * 16 + 2 * i + 1] = v.y;
        }
    }
#pragma unroll
    for (int i = 0; i < 8; i++) {
        ulonglong2 v = *(const ulonglong2*)(V2 + (128 + r) * 128 + (4 * i + q) * 4);
        W.w2b[2 * i] = v.x; W.w2b[2 * i + 1] = v.y;
    }

    // ---- stage small constants into SMEM ----
    for (int i = t; i < 2048; i += NTHREADS) sm[OFF_R + i] = R[i];
    if (t < 32) sm[OFF_RB + t] = rb[t];
    if (t < 128) { sm[OFF_C0 + t] = c0[t]; sm[OFF_C1 + t] = c1[t]; }
    if (t < 192) sm[OFF_C2 + t] = c2[t];

    // ---- per-batch: dt array ----
    {
        const float* tsb = ts + b * TLEN;
        for (int i = t; i < NSTEP; i += NTHREADS) sm[OFF_DTS + i] = tsb[i + 1] - tsb[i];
    }

    // ---- per-batch: window log-signature slopes (16 windows x 6 channels) ----
    if (t < NWIN) {
        const float* xp = x + (b * TLEN + t * 8) * 3;
        float p[9][3];
#pragma unroll
        for (int k = 0; k < 9; k++) {
            p[k][0] = xp[k * 3 + 0];
            p[k][1] = xp[k * 3 + 1];
            p[k][2] = xp[k * 3 + 2];
        }
        float a01 = 0.f, a10 = 0.f, a02 = 0.f, a20 = 0.f, a12 = 0.f, a21 = 0.f;
#pragma unroll
        for (int k = 0; k < 8; k++) {
            float r0 = p[k][0] - p[0][0], r1 = p[k][1] - p[0][1], r2 = p[k][2] - p[0][2];
            float d0 = p[k + 1][0] - p[k][0], d1 = p[k + 1][1] - p[k][1], d2 = p[k + 1][2] - p[k][2];
            a01 = fmaf(r0, d1, a01); a10 = fmaf(r1, d0, a10);
            a02 = fmaf(r0, d2, a02); a20 = fmaf(r2, d0, a20);
            a12 = fmaf(r1, d2, a12); a21 = fmaf(r2, d1, a21);
        }
        const float* tsb = ts + b * TLEN;
        float td = tsb[(t + 1) * 8] - tsb[t * 8];
        float* sl = sm + OFF_SLP + t * 8;
        sl[0] = (p[8][0] - p[0][0]) / td;
        sl[1] = (p[8][1] - p[0][1]) / td;
        sl[2] = (p[8][2] - p[0][2]) / td;
        sl[3] = (0.5f * (a01 - a10)) / td;
        sl[4] = (0.5f * (a02 - a20)) / td;
        sl[5] = (0.5f * (a12 - a21)) / td;
    }
    __syncthreads();

    // ---- init MLP: h0 = W2 @ sp(W1 @ sp(W0 @ x0 + b0) + b1) + b2 ----
    if (t < 128) {
        const float* xp = x + b * TLEN * 3;
        float x0 = xp[0], x1 = xp[1], x2 = xp[2];
        float u = b0[t] + W0[t * 3] * x0 + W0[t * 3 + 1] * x1 + W0[t * 3 + 2] * x2;
        sm[OFF_S0 + t] = softplusf(u);
    }
    __syncthreads();
    if (t < 128) {
        float acc = b1[t];
        const float* w = W1 + t * 128;
#pragma unroll 4
        for (int j = 0; j < 128; j++) acc = fmaf(w[j], sm[OFF_S0 + j], acc);
        sm[OFF_S1 + t] = softplusf(acc);
    }
    __syncthreads();
    if (t < 64) {
        float acc = b2[t];
        const float* w = W2 + t * 128;
#pragma unroll 4
        for (int j = 0; j < 128; j++) acc = fmaf(w[j], sm[OFF_S1 + j], acc);
        sm[OFF_Y + t] = acc;
    }
    __syncthreads();

    // ---- output row 0 (from h0) ----
    write_out_row(sm, t, out + (b * TLEN + 0) * OUTN);

    // ---- RK2 (Heun) scan over 128 steps ----
    for (int i = 0; i < NSTEP; i++) {
        float dt = sm[OFF_DTS + i];
        const float* svec = sm + OFF_SLP + ((i >> 3) << 3);

        float k1 = eval_F(sm, t, sm + OFF_Y, svec, W);
        if (t < 64) sm[OFF_Y2 + t] = sm[OFF_Y + t] + dt * k1;
        __syncthreads();

        float k2 = eval_F(sm, t, sm + OFF_Y2, svec, W);
        if (t < 64) sm[OFF_Y + t] += 0.5f * dt * (k1 + k2);
        __syncthreads();

        write_out_row(sm, t, out + (b * TLEN + i + 1) * OUTN);
    }
}

extern "C" void kernel_launch(void* const* d_in, const int* in_sizes, int n_in,
                              void* d_out, int out_size)
{
    const float* ts = (const float*)d_in[0];
    const float* x  = (const float*)d_in[1];
    const float* W0 = (const float*)d_in[2];
    const float* b0 = (const float*)d_in[3];
    const float* W1 = (const float*)d_in[4];
    const float* b1 = (const float*)d_in[5];
    const float* W2 = (const float*)d_in[6];
    const float* b2 = (const float*)d_in[7];
    const float* V0 = (const float*)d_in[8];
    const float* c0 = (const float*)d_in[9];
    const float* V1 = (const float*)d_in[10];
    const float* c1 = (const float*)d_in[11];
    const float* V2 = (const float*)d_in[12];
    const float* c2 = (const float*)d_in[13];
    const float* R  = (const float*)d_in[14];
    const float* rb = (const float*)d_in[15];
    float* out = (float*)d_out;

    cudaFuncSetAttribute(ncde_kernel, cudaFuncAttributeMaxDynamicSharedMemorySize, SMEM_BYTES);
    ncde_kernel<<<BATCH, NTHREADS, SMEM_BYTES>>>(ts, x, W0, b0, W1, b1, W2, b2,
                                                 V0, c0, V1, c1, V2, c2, R, rb, out);
}

// round 12
// speedup vs baseline: 2.1017x; 1.1909x over previous
#include <cuda_runtime.h>
#include <math.h>

// Problem constants
#define NTHREADS 256
#define BATCH    128
#define TLEN     129
#define NSTEP    128   // TLEN-1
#define NWIN     16    // (TLEN-1)/8
#define OUTN     32

// ---- shared memory layout (float offsets) ----
// ALL weights live in per-thread registers (packed f32x2).
// Thread t = 4r+q (r<64,q<4) owns rows {r, r+64} of V0/V1/V2[0:128],
// row 128+r of V2[128:192], K-quarter q (float4 indices 4i+q).
#define OFF_R    0        // 2048  (R row-major 32x64)
#define OFF_RB   2048     // 32
#define OFF_C0   2080     // 128
#define OFF_C1   2208     // 128
#define OFF_C2   2336     // 192
#define OFF_Y    2528     // 64
#define OFF_Y2   2592     // 64
#define OFF_S0   2656     // 128
#define OFF_S1   2784     // 128
#define OFF_M    2912     // 192
#define OFF_TN0  3104     // 3*128
#define OFF_TN1  3488     // 3*128
#define OFF_SLP  3872     // 16*8 (6 used per window)
#define OFF_DTS  4000     // 128
#define SMEM_FLOATS 4128
#define SMEM_BYTES  (SMEM_FLOATS * 4)

typedef unsigned long long u64;

// ---- fast transcendentals (MUFU-based; rel err ~1e-7, budget is 1e-3) ----
__device__ __forceinline__ float frcp_(float x) {
    float r;
    asm("rcp.approx.ftz.f32 %0, %1;" : "=f"(r) : "f"(x));
    return r;
}
// softplus + sigmoid sharing one exp:
//   e = exp(-|u|); sp = max(u,0)+log(1+e); sig = u>0 ? 1/(1+e) : e/(1+e)
__device__ __forceinline__ void sp_sig(float u, float& sp, float& g) {
    float e = __expf(-fabsf(u));
    float den = frcp_(1.0f + e);
    sp = fmaxf(u, 0.0f) + __logf(1.0f + e);
    g = (u > 0.0f) ? den : e * den;
}
// tanh + (1-tanh^2):  m = 1 - 2/(1+exp(2z))  (overflow -> inf -> rcp=0 -> m=1)
__device__ __forceinline__ void tanh_tz(float z, float& m, float& tz) {
    float e2 = __expf(2.0f * z);
    float w = frcp_(1.0f + e2);
    m = fmaf(-2.0f, w, 1.0f);
    tz = 1.0f - m * m;
}
__device__ __forceinline__ float ftanh(float z) {
    float e2 = __expf(2.0f * z);
    return fmaf(-2.0f, frcp_(1.0f + e2), 1.0f);
}

// packed f32x2 fma: lanewise d = a*b + c
__device__ __forceinline__ u64 ffma2(u64 a, u64 b, u64 c) {
    u64 d;
    asm("fma.rn.f32x2 %0, %1, %2, %3;" : "=l"(d) : "l"(a), "l"(b), "l"(c));
    return d;
}
// horizontal add of the two f32 lanes
__device__ __forceinline__ float hadd2(u64 v) {
    unsigned lo, hi;
    asm("mov.b64 {%0, %1}, %2;" : "=r"(lo), "=r"(hi) : "l"(v));
    return __uint_as_float(lo) + __uint_as_float(hi);
}
// LDS.128 into two packed f32x2 (64-bit register pairs)
__device__ __forceinline__ void lds_v2u64(const float* p, u64& a, u64& b) {
    unsigned addr = (unsigned)__cvta_generic_to_shared(p);
    asm volatile("ld.shared.v2.u64 {%0, %1}, [%2];" : "=l"(a), "=l"(b) : "r"(addr));
}
// butterfly reduce over 4 consecutive lanes (result valid in ALL lanes)
__device__ __forceinline__ float qred(float s) {
    s += __shfl_xor_sync(0xffffffffu, s, 1);
    s += __shfl_xor_sync(0xffffffffu, s, 2);
    return s;
}

// Persistent per-thread register-resident weights
struct FState {
    u64 w0[16];   // V0 rows r,r+64   : [row01*8  + 2i + j], i<4
    u64 w1[32];   // V1 rows r,r+64   : [row01*16 + 2i + j], i<8
    u64 w2a[32];  // V2 rows r,r+64   : [row01*16 + 2i + j], i<8
    u64 w2b[16];  // V2 row 128+r     : [2i + j], i<8
};

// F(y) . s. 256 threads, row-pair x quarter-K split, all weights in registers.
// Returns k[r] (valid in ALL lanes of quad r; caller predicates the write).
// NO trailing barrier — caller must __syncthreads() after consuming k.
__device__ __forceinline__ float eval_F(float* sm, int tid,
                                        const float* __restrict__ yin,
                                        const float* __restrict__ svec,
                                        const FState& W)
{
    const int r = tid >> 2, q = tid & 3;
    float* s0  = sm + OFF_S0;
    float* s1  = sm + OFF_S1;
    float* msm = sm + OFF_M;
    float* tn0 = sm + OFF_TN0;
    float* tn1 = sm + OFF_TN1;

    float g0a, g0b, g1a, g1b;              // sigmoid gates (all lanes)
    float ma, mb, mc, tza, tzb, tzc;       // tanh outputs + derivs (all lanes)

    // ---------- forward layer 0: u0 = V0 @ y + c0 (K=64) ----------
    {
        u64 acc0 = 0ull, acc1 = 0ull;
#pragma unroll
        for (int i = 0; i < 4; i++) {
            u64 a0, a1;
            lds_v2u64(yin + (4 * i + q) * 4, a0, a1);
            acc0 = ffma2(W.w0[2 * i], a0, acc0);
            acc0 = ffma2(W.w0[2 * i + 1], a1, acc0);
            acc1 = ffma2(W.w0[8 + 2 * i], a0, acc1);
            acc1 = ffma2(W.w0[8 + 2 * i + 1], a1, acc1);
        }
        float sa = qred(hadd2(acc0));
        float sb = qred(hadd2(acc1));
        float ua = sm[OFF_C0 + r] + sa;
        float ub = sm[OFF_C0 + r + 64] + sb;
        float spa, spb;
        sp_sig(ua, spa, g0a);
        sp_sig(ub, spb, g0b);
        if (q == 0) { s0[r] = spa; s0[r + 64] = spb; }
    }
    __syncthreads();
    // ---------- forward layer 1 (K=128) ----------
    {
        u64 acc0 = 0ull, acc1 = 0ull;
#pragma unroll
        for (int i = 0; i < 8; i++) {
            u64 a0, a1;
            lds_v2u64(s0 + (4 * i + q) * 4, a0, a1);
            acc0 = ffma2(W.w1[2 * i], a0, acc0);
            acc0 = ffma2(W.w1[2 * i + 1], a1, acc0);
            acc1 = ffma2(W.w1[16 + 2 * i], a0, acc1);
            acc1 = ffma2(W.w1[16 + 2 * i + 1], a1, acc1);
        }
        float sa = qred(hadd2(acc0));
        float sb = qred(hadd2(acc1));
        float ua = sm[OFF_C1 + r] + sa;
        float ub = sm[OFF_C1 + r + 64] + sb;
        float spa, spb;
        sp_sig(ua, spa, g1a);
        sp_sig(ub, spb, g1b);
        if (q == 0) { s1[r] = spa; s1[r + 64] = spb; }
    }
    __syncthreads();
    // ---------- forward layer 2 (192 rows: r, r+64, 128+r) ----------
    {
        u64 acc0 = 0ull, acc1 = 0ull, acc2 = 0ull;
#pragma unroll
        for (int i = 0; i < 8; i++) {
            u64 a0, a1;
            lds_v2u64(s1 + (4 * i + q) * 4, a0, a1);
            acc0 = ffma2(W.w2a[2 * i], a0, acc0);
            acc0 = ffma2(W.w2a[2 * i + 1], a1, acc0);
            acc1 = ffma2(W.w2a[16 + 2 * i], a0, acc1);
            acc1 = ffma2(W.w2a[16 + 2 * i + 1], a1, acc1);
            acc2 = ffma2(W.w2b[2 * i], a0, acc2);
            acc2 = ffma2(W.w2b[2 * i + 1], a1, acc2);
        }
        float sa = qred(hadd2(acc0));
        float sb = qred(hadd2(acc1));
        float sc = qred(hadd2(acc2));
        tanh_tz(sm[OFF_C2 + r] + sa, ma, tza);
        tanh_tz(sm[OFF_C2 + r + 64] + sb, mb, tzb);
        tanh_tz(sm[OFF_C2 + 128 + r] + sc, mc, tzc);
        if (q == 0) { msm[r] = ma; msm[r + 64] = mb; msm[128 + r] = mc; }
    }
    __syncthreads();
    // ---------- JVP layer 0 (3 tangents = rows of m; K=64) ----------
    {
        u64 d00 = 0ull, d01 = 0ull, d02 = 0ull;
        u64 d10 = 0ull, d11 = 0ull, d12 = 0ull;
#pragma unroll
        for (int i = 0; i < 4; i++) {
            u64 a0, a1, b0, b1, c0v, c1v;
            lds_v2u64(msm + (4 * i + q) * 4, a0, a1);
            lds_v2u64(msm + 64 + (4 * i + q) * 4, b0, b1);
            lds_v2u64(msm + 128 + (4 * i + q) * 4, c0v, c1v);
            u64 wa0 = W.w0[2 * i], wa1 = W.w0[2 * i + 1];
            u64 wb0 = W.w0[8 + 2 * i], wb1 = W.w0[8 + 2 * i + 1];
            d00 = ffma2(wa0, a0, d00);  d00 = ffma2(wa1, a1, d00);
            d01 = ffma2(wa0, b0, d01);  d01 = ffma2(wa1, b1, d01);
            d02 = ffma2(wa0, c0v, d02); d02 = ffma2(wa1, c1v, d02);
            d10 = ffma2(wb0, a0, d10);  d10 = ffma2(wb1, a1, d10);
            d11 = ffma2(wb0, b0, d11);  d11 = ffma2(wb1, b1, d11);
            d12 = ffma2(wb0, c0v, d12); d12 = ffma2(wb1, c1v, d12);
        }
        float e00 = qred(hadd2(d00)), e01 = qred(hadd2(d01)), e02 = qred(hadd2(d02));
        float e10 = qred(hadd2(d10)), e11 = qred(hadd2(d11)), e12 = qred(hadd2(d12));
        if (q == 0) {
            tn0[r]            = g0a * e00;
            tn0[128 + r]      = g0a * e01;
            tn0[256 + r]      = g0a * e02;
            tn0[r + 64]       = g0b * e10;
            tn0[128 + r + 64] = g0b * e11;
            tn0[256 + r + 64] = g0b * e12;
        }
    }
    __syncthreads();
    // ---------- JVP layer 1 (K=128) ----------
    {
        u64 d00 = 0ull, d01 = 0ull, d02 = 0ull;
        u64 d10 = 0ull, d11 = 0ull, d12 = 0ull;
#pragma unroll
        for (int i = 0; i < 8; i++) {
            u64 a0, a1, b0, b1, c0v, c1v;
            lds_v2u64(tn0 + (4 * i + q) * 4, a0, a1);
            lds_v2u64(tn0 + 128 + (4 * i + q) * 4, b0, b1);
            lds_v2u64(tn0 + 256 + (4 * i + q) * 4, c0v, c1v);
            u64 wa0 = W.w1[2 * i], wa1 = W.w1[2 * i + 1];
            u64 wb0 = W.w1[16 + 2 * i], wb1 = W.w1[16 + 2 * i + 1];
            d00 = ffma2(wa0, a0, d00);  d00 = ffma2(wa1, a1, d00);
            d01 = ffma2(wa0, b0, d01);  d01 = ffma2(wa1, b1, d01);
            d02 = ffma2(wa0, c0v, d02); d02 = ffma2(wa1, c1v, d02);
            d10 = ffma2(wb0, a0, d10);  d10 = ffma2(wb1, a1, d10);
            d11 = ffma2(wb0, b0, d11);  d11 = ffma2(wb1, b1, d11);
            d12 = ffma2(wb0, c0v, d12); d12 = ffma2(wb1, c1v, d12);
        }
        float e00 = qred(hadd2(d00)), e01 = qred(hadd2(d01)), e02 = qred(hadd2(d02));
        float e10 = qred(hadd2(d10)), e11 = qred(hadd2(d11)), e12 = qred(hadd2(d12));
        if (q == 0) {
            tn1[r]            = g1a * e00;
            tn1[128 + r]      = g1a * e01;
            tn1[256 + r]      = g1a * e02;
            tn1[r + 64]       = g1b * e10;
            tn1[128 + r + 64] = g1b * e11;
            tn1[256 + r + 64] = g1b * e12;
        }
    }
    __syncthreads();
    // ---------- JVP layer 2 — only the 6 J-blocks the bracket uses ----------
    // k[r] needs exactly: tangent0 rows {r+64, 128+r}, tangent1 rows {r, 128+r},
    // tangent2 rows {r, r+64} — all owned by THIS quad. No J smem, no combine stage.
    {
        u64 d01 = 0ull, d02 = 0ull;    // row r       x tangents 1,2
        u64 d10 = 0ull, d12 = 0ull;    // row r+64    x tangents 0,2
        u64 d20 = 0ull, d21 = 0ull;    // row 128+r   x tangents 0,1
#pragma unroll
        for (int i = 0; i < 8; i++) {
            u64 a0, a1, b0, b1, c0v, c1v;
            lds_v2u64(tn1 + (4 * i + q) * 4, a0, a1);
            lds_v2u64(tn1 + 128 + (4 * i + q) * 4, b0, b1);
            lds_v2u64(tn1 + 256 + (4 * i + q) * 4, c0v, c1v);
            u64 wa0 = W.w2a[2 * i], wa1 = W.w2a[2 * i + 1];
            u64 wb0 = W.w2a[16 + 2 * i], wb1 = W.w2a[16 + 2 * i + 1];
            u64 wc0 = W.w2b[2 * i], wc1 = W.w2b[2 * i + 1];
            d01 = ffma2(wa0, b0, d01);  d01 = ffma2(wa1, b1, d01);
            d02 = ffma2(wa0, c0v, d02); d02 = ffma2(wa1, c1v, d02);
            d10 = ffma2(wb0, a0, d10);  d10 = ffma2(wb1, a1, d10);
            d12 = ffma2(wb0, c0v, d12); d12 = ffma2(wb1, c1v, d12);
            d20 = ffma2(wc0, a0, d20);  d20 = ffma2(wc1, a1, d20);
            d21 = ffma2(wc0, b0, d21);  d21 = ffma2(wc1, b1, d21);
        }
        float e01 = qred(hadd2(d01)), e02 = qred(hadd2(d02));
        float e10 = qred(hadd2(d10)), e12 = qred(hadd2(d12));
        float e20 = qred(hadd2(d20)), e21 = qred(hadd2(d21));
        // br(0,1) = J_t0[64+r] - J_t1[r]; br(0,2) = J_t0[128+r] - J_t2[r];
        // br(1,2) = J_t1[128+r] - J_t2[64+r]
        float br01 = tzb * e10 - tza * e01;
        float br02 = tzc * e20 - tza * e02;
        float br12 = tzc * e21 - tzb * e12;
        float k =  ma * svec[0] + mb * svec[1] + mc * svec[2]
                 + br01 * svec[3] + br02 * svec[4] + br12 * svec[5];
        return k;
    }
}

// Output projection: out_row[o] = tanh(dot(y, R[o,:]) + rb[o])
// 256 threads: 8 threads per output, 8-dim partials, shuffle-reduce.
__device__ __forceinline__ void write_out_row(const float* sm, int t, float* __restrict__ dst)
{
    int o = t >> 3, part = t & 7;
    const float* r = sm + OFF_R + o * 64 + part * 8;
    const float* y = sm + OFF_Y + part * 8;
    float s = 0.f;
#pragma unroll
    for (int j = 0; j < 8; j++) s = fmaf(r[j], y[j], s);
    s += __shfl_xor_sync(0xffffffffu, s, 1);
    s += __shfl_xor_sync(0xffffffffu, s, 2);
    s += __shfl_xor_sync(0xffffffffu, s, 4);
    if (part == 0) dst[o] = ftanh(s + sm[OFF_RB + o]);
}

__global__ void __launch_bounds__(NTHREADS, 1)
ncde_kernel(const float* __restrict__ ts, const float* __restrict__ x,
            const float* __restrict__ W0, const float* __restrict__ b0,
            const float* __restrict__ W1, const float* __restrict__ b1,
            const float* __restrict__ W2, const float* __restrict__ b2,
            const float* __restrict__ V0, const float* __restrict__ c0,
            const float* __restrict__ V1, const float* __restrict__ c1,
            const float* __restrict__ V2, const float* __restrict__ c2,
            const float* __restrict__ R,  const float* __restrict__ rb,
            float* __restrict__ out)
{
    extern __shared__ float sm[];
    const int t = threadIdx.x;
    const int b = blockIdx.x;
    const int r = t >> 2, q = t & 3;

    // ---- pin per-thread weight slices in registers (packed f32x2) ----
    FState W;
#pragma unroll
    for (int ro = 0; ro < 2; ro++) {
        int row = r + 64 * ro;
#pragma unroll
        for (int i = 0; i < 4; i++) {
            ulonglong2 v = *(const ulonglong2*)(V0 + row * 64 + (4 * i + q) * 4);
            W.w0[ro * 8 + 2 * i] = v.x; W.w0[ro * 8 + 2 * i + 1] = v.y;
        }
#pragma unroll
        for (int i = 0; i < 8; i++) {
            ulonglong2 v = *(const ulonglong2*)(V1 + row * 128 + (4 * i + q) * 4);
            W.w1[ro * 16 + 2 * i] = v.x; W.w1[ro * 16 + 2 * i + 1] = v.y;
        }
#pragma unroll
        for (int i = 0; i < 8; i++) {
            ulonglong2 v = *(const ulonglong2*)(V2 + row * 128 + (4 * i + q) * 4);
            W.w2a[ro * 16 + 2 * i] = v.x; W.w2a[ro * 16 + 2 * i + 1] = v.y;
        }
    }
#pragma unroll
    for (int i = 0; i < 8; i++) {
        ulonglong2 v = *(const ulonglong2*)(V2 + (128 + r) * 128 + (4 * i + q) * 4);
        W.w2b[2 * i] = v.x; W.w2b[2 * i + 1] = v.y;
    }

    // ---- stage small constants into SMEM ----
    for (int i = t; i < 2048; i += NTHREADS) sm[OFF_R + i] = R[i];
    if (t < 32) sm[OFF_RB + t] = rb[t];
    if (t < 128) { sm[OFF_C0 + t] = c0[t]; sm[OFF_C1 + t] = c1[t]; }
    if (t < 192) sm[OFF_C2 + t] = c2[t];

    // ---- per-batch: dt array ----
    {
        const float* tsb = ts + b * TLEN;
        for (int i = t; i < NSTEP; i += NTHREADS) sm[OFF_DTS + i] = tsb[i + 1] - tsb[i];
    }

    // ---- per-batch: window log-signature slopes (16 windows x 6 channels) ----
    if (t < NWIN) {
        const float* xp = x + (b * TLEN + t * 8) * 3;
        float p[9][3];
#pragma unroll
        for (int k = 0; k < 9; k++) {
            p[k][0] = xp[k * 3 + 0];
            p[k][1] = xp[k * 3 + 1];
            p[k][2] = xp[k * 3 + 2];
        }
        float a01 = 0.f, a10 = 0.f, a02 = 0.f, a20 = 0.f, a12 = 0.f, a21 = 0.f;
#pragma unroll
        for (int k = 0; k < 8; k++) {
            float r0 = p[k][0] - p[0][0], r1 = p[k][1] - p[0][1], r2 = p[k][2] - p[0][2];
            float d0 = p[k + 1][0] - p[k][0], d1 = p[k + 1][1] - p[k][1], d2 = p[k + 1][2] - p[k][2];
            a01 = fmaf(r0, d1, a01); a10 = fmaf(r1, d0, a10);
            a02 = fmaf(r0, d2, a02); a20 = fmaf(r2, d0, a20);
            a12 = fmaf(r1, d2, a12); a21 = fmaf(r2, d1, a21);
        }
        const float* tsb = ts + b * TLEN;
        float td = tsb[(t + 1) * 8] - tsb[t * 8];
        float* sl = sm + OFF_SLP + t * 8;
        sl[0] = (p[8][0] - p[0][0]) / td;
        sl[1] = (p[8][1] - p[0][1]) / td;
        sl[2] = (p[8][2] - p[0][2]) / td;
        sl[3] = (0.5f * (a01 - a10)) / td;
        sl[4] = (0.5f * (a02 - a20)) / td;
        sl[5] = (0.5f * (a12 - a21)) / td;
    }
    __syncthreads();

    // ---- init MLP: h0 = W2 @ sp(W1 @ sp(W0 @ x0 + b0) + b1) + b2 ----
    if (t < 128) {
        const float* xp = x + b * TLEN * 3;
        float x0 = xp[0], x1 = xp[1], x2 = xp[2];
        float u = b0[t] + W0[t * 3] * x0 + W0[t * 3 + 1] * x1 + W0[t * 3 + 2] * x2;
        float sp, gdummy;
        sp_sig(u, sp, gdummy);
        sm[OFF_S0 + t] = sp;
    }
    __syncthreads();
    if (t < 128) {
        float acc = b1[t];
        const float* w = W1 + t * 128;
#pragma unroll 4
        for (int j = 0; j < 128; j++) acc = fmaf(w[j], sm[OFF_S0 + j], acc);
        float sp, gdummy;
        sp_sig(acc, sp, gdummy);
        sm[OFF_S1 + t] = sp;
    }
    __syncthreads();
    if (t < 64) {
        float acc = b2[t];
        const float* w = W2 + t * 128;
#pragma unroll 4
        for (int j = 0; j < 128; j++) acc = fmaf(w[j], sm[OFF_S1 + j], acc);
        sm[OFF_Y + t] = acc;
    }
    __syncthreads();

    // ---- output row 0 (from h0) ----
    write_out_row(sm, t, out + (b * TLEN + 0) * OUTN);

    // ---- RK2 (Heun) scan over 128 steps ----
    for (int i = 0; i < NSTEP; i++) {
        float dt = sm[OFF_DTS + i];
        const float* svec = sm + OFF_SLP + ((i >> 3) << 3);

        float k1 = eval_F(sm, t, sm + OFF_Y, svec, W);
        if (q == 0) sm[OFF_Y2 + r] = sm[OFF_Y + r] + dt * k1;
        __syncthreads();

        float k2 = eval_F(sm, t, sm + OFF_Y2, svec, W);
        if (q == 0) sm[OFF_Y + r] = sm[OFF_Y + r] + 0.5f * dt * (k1 + k2);
        __syncthreads();

        write_out_row(sm, t, out + (b * TLEN + i + 1) * OUTN);
    }
}

extern "C" void kernel_launch(void* const* d_in, const int* in_sizes, int n_in,
                              void* d_out, int out_size)
{
    const float* ts = (const float*)d_in[0];
    const float* x  = (const float*)d_in[1];
    const float* W0 = (const float*)d_in[2];
    const float* b0 = (const float*)d_in[3];
    const float* W1 = (const float*)d_in[4];
    const float* b1 = (const float*)d_in[5];
    const float* W2 = (const float*)d_in[6];
    const float* b2 = (const float*)d_in[7];
    const float* V0 = (const float*)d_in[8];
    const float* c0 = (const float*)d_in[9];
    const float* V1 = (const float*)d_in[10];
    const float* c1 = (const float*)d_in[11];
    const float* V2 = (const float*)d_in[12];
    const float* c2 = (const float*)d_in[13];
    const float* R  = (const float*)d_in[14];
    const float* rb = (const float*)d_in[15];
    float* out = (float*)d_out;

    cudaFuncSetAttribute(ncde_kernel, cudaFuncAttributeMaxDynamicSharedMemorySize, SMEM_BYTES);
    ncde_kernel<<<BATCH, NTHREADS, SMEM_BYTES>>>(ts, x, W0, b0, W1, b1, W2, b2,
                                                 V0, c0, V1, c1, V2, c2, R, rb, out);
}

// round 13
// speedup vs baseline: 2.1749x; 1.0348x over previous
#include <cuda_runtime.h>
#include <math.h>

// Problem constants
#define NTHREADS 256
#define BATCH    128
#define TLEN     129
#define NSTEP    128   // TLEN-1
#define NWIN     16    // (TLEN-1)/8
#define OUTN     32

// ---- shared memory layout (float offsets) ----
// ALL weights live in per-thread registers (packed f32x2).
// Thread t = 4r+q (r<64,q<4) owns rows {r, r+64} of V0/V1/V2[0:128],
// row 128+r of V2[128:192], K-quarter q (float4 indices 4i+q).
#define OFF_R    0        // 2048  (R row-major 32x64)
#define OFF_RB   2048     // 32
#define OFF_C0   2080     // 128
#define OFF_C1   2208     // 128
#define OFF_C2   2336     // 192
#define OFF_Y    2528     // 64
#define OFF_Y2   2592     // 64
#define OFF_S0   2656     // 128
#define OFF_S1   2784     // 128
#define OFF_M    2912     // 192
#define OFF_TN0  3104     // 3*128
#define OFF_TN1  3488     // 3*128
#define OFF_SLP  3872     // 16*8 (6 used per window)
#define OFF_DTS  4000     // 128
#define SMEM_FLOATS 4128
#define SMEM_BYTES  (SMEM_FLOATS * 4)

typedef unsigned long long u64;

// ---- fast transcendentals (MUFU-based; rel err ~1e-7, budget is 1e-3) ----
__device__ __forceinline__ float frcp_(float x) {
    float r;
    asm("rcp.approx.ftz.f32 %0, %1;" : "=f"(r) : "f"(x));
    return r;
}
// softplus + sigmoid sharing one exp:
//   e = exp(-|u|); sp = max(u,0)+log(1+e); sig = u>0 ? 1/(1+e) : e/(1+e)
__device__ __forceinline__ void sp_sig(float u, float& sp, float& g) {
    float e = __expf(-fabsf(u));
    float den = frcp_(1.0f + e);
    sp = fmaxf(u, 0.0f) + __logf(1.0f + e);
    g = (u > 0.0f) ? den : e * den;
}
// tanh + (1-tanh^2):  m = 1 - 2/(1+exp(2z))  (overflow -> inf -> rcp=0 -> m=1)
__device__ __forceinline__ void tanh_tz(float z, float& m, float& tz) {
    float e2 = __expf(2.0f * z);
    float w = frcp_(1.0f + e2);
    m = fmaf(-2.0f, w, 1.0f);
    tz = 1.0f - m * m;
}
__device__ __forceinline__ float ftanh(float z) {
    float e2 = __expf(2.0f * z);
    return fmaf(-2.0f, frcp_(1.0f + e2), 1.0f);
}

// packed f32x2 fma: lanewise d = a*b + c
__device__ __forceinline__ u64 ffma2(u64 a, u64 b, u64 c) {
    u64 d;
    asm("fma.rn.f32x2 %0, %1, %2, %3;" : "=l"(d) : "l"(a), "l"(b), "l"(c));
    return d;
}
// horizontal add of the two f32 lanes
__device__ __forceinline__ float hadd2(u64 v) {
    unsigned lo, hi;
    asm("mov.b64 {%0, %1}, %2;" : "=r"(lo), "=r"(hi) : "l"(v));
    return __uint_as_float(lo) + __uint_as_float(hi);
}
// LDS.128 into two packed f32x2 (64-bit register pairs)
__device__ __forceinline__ void lds_v2u64(const float* p, u64& a, u64& b) {
    unsigned addr = (unsigned)__cvta_generic_to_shared(p);
    asm volatile("ld.shared.v2.u64 {%0, %1}, [%2];" : "=l"(a), "=l"(b) : "r"(addr));
}
// standard butterfly reduce over 4 consecutive lanes (result valid in ALL lanes)
__device__ __forceinline__ float qred(float s) {
    s += __shfl_xor_sync(0xffffffffu, s, 1);
    s += __shfl_xor_sync(0xffffffffu, s, 2);
    return s;
}
// value-routed quad reduce of a row-pair (ea: row A partial, eb: row B partial).
// Returns my-parity row's FULL quad sum: even lanes -> sum(ea), odd -> sum(eb).
// Tree is (q0+q1)+(q2+q3), identical to qred.
__device__ __forceinline__ float qred_routed(float ea, float eb, int par) {
    float send = par ? ea : eb;
    float recv = __shfl_xor_sync(0xffffffffu, send, 1);
    float kept = (par ? eb : ea) + recv;
    kept += __shfl_xor_sync(0xffffffffu, kept, 2);
    return kept;
}

// Persistent per-thread register-resident weights
struct FState {
    u64 w0[16];   // V0 rows r,r+64   : [row01*8  + 2i + j], i<4
    u64 w1[32];   // V1 rows r,r+64   : [row01*16 + 2i + j], i<8
    u64 w2a[32];  // V2 rows r,r+64   : [row01*16 + 2i + j], i<8
    u64 w2b[16];  // V2 row 128+r     : [2i + j], i<8
};

// F(y) . s. 256 threads, row-pair x quarter-K split, all weights in registers.
// Parity-routed reductions: even lanes carry row r, odd lanes row r+64.
// Returns k[r] valid on EVEN lanes (caller uses q==0).
// NO trailing barrier — caller must __syncthreads() after consuming k.
__device__ __forceinline__ float eval_F(float* sm, int tid,
                                        const float* __restrict__ yin,
                                        const float* __restrict__ svec,
                                        const FState& W)
{
    const int r = tid >> 2, q = tid & 3;
    const int par = q & 1;                   // 0: row r, 1: row r+64
    const int rowoff = par ? 64 : 0;
    float* s0  = sm + OFF_S0;
    float* s1  = sm + OFF_S1;
    float* msm = sm + OFF_M;
    float* tn0 = sm + OFF_TN0;
    float* tn1 = sm + OFF_TN1;

    float g0p, g1p;            // sigmoid gates for my parity row
    float m_ab, tz_ab;         // tanh for my parity row
    float mc, tzc;             // tanh row 128+r (all lanes)

    // ---------- forward layer 0: u0 = V0 @ y + c0 (K=64) ----------
    {
        u64 acc0 = 0ull, acc1 = 0ull;
#pragma unroll
        for (int i = 0; i < 4; i++) {
            u64 a0, a1;
            lds_v2u64(yin + (4 * i + q) * 4, a0, a1);
            acc0 = ffma2(W.w0[2 * i], a0, acc0);
            acc0 = ffma2(W.w0[2 * i + 1], a1, acc0);
            acc1 = ffma2(W.w0[8 + 2 * i], a0, acc1);
            acc1 = ffma2(W.w0[8 + 2 * i + 1], a1, acc1);
        }
        float kept = qred_routed(hadd2(acc0), hadd2(acc1), par);
        float u = sm[OFF_C0 + r + rowoff] + kept;
        float sp;
        sp_sig(u, sp, g0p);
        if (q < 2) s0[r + q * 64] = sp;
    }
    __syncthreads();
    // ---------- forward layer 1 (K=128) ----------
    {
        u64 acc0 = 0ull, acc1 = 0ull;
#pragma unroll
        for (int i = 0; i < 8; i++) {
            u64 a0, a1;
            lds_v2u64(s0 + (4 * i + q) * 4, a0, a1);
            acc0 = ffma2(W.w1[2 * i], a0, acc0);
            acc0 = ffma2(W.w1[2 * i + 1], a1, acc0);
            acc1 = ffma2(W.w1[16 + 2 * i], a0, acc1);
            acc1 = ffma2(W.w1[16 + 2 * i + 1], a1, acc1);
        }
        float kept = qred_routed(hadd2(acc0), hadd2(acc1), par);
        float u = sm[OFF_C1 + r + rowoff] + kept;
        float sp;
        sp_sig(u, sp, g1p);
        if (q < 2) s1[r + q * 64] = sp;
    }
    __syncthreads();
    // ---------- forward layer 2 (192 rows: r/r+64 routed, 128+r all-lane) ----------
    {
        u64 acc0 = 0ull, acc1 = 0ull, acc2 = 0ull;
#pragma unroll
        for (int i = 0; i < 8; i++) {
            u64 a0, a1;
            lds_v2u64(s1 + (4 * i + q) * 4, a0, a1);
            acc0 = ffma2(W.w2a[2 * i], a0, acc0);
            acc0 = ffma2(W.w2a[2 * i + 1], a1, acc0);
            acc1 = ffma2(W.w2a[16 + 2 * i], a0, acc1);
            acc1 = ffma2(W.w2a[16 + 2 * i + 1], a1, acc1);
            acc2 = ffma2(W.w2b[2 * i], a0, acc2);
            acc2 = ffma2(W.w2b[2 * i + 1], a1, acc2);
        }
        float kab = qred_routed(hadd2(acc0), hadd2(acc1), par);
        float sc  = qred(hadd2(acc2));
        tanh_tz(sm[OFF_C2 + r + rowoff] + kab, m_ab, tz_ab);
        tanh_tz(sm[OFF_C2 + 128 + r] + sc, mc, tzc);
        if (q < 2) msm[r + q * 64] = m_ab;
        if (q == 0) msm[128 + r] = mc;
    }
    __syncthreads();
    // ---------- JVP layer 0 (3 tangents = rows of m; K=64) ----------
    {
        u64 d00 = 0ull, d01 = 0ull, d02 = 0ull;
        u64 d10 = 0ull, d11 = 0ull, d12 = 0ull;
#pragma unroll
        for (int i = 0; i < 4; i++) {
            u64 a0, a1, b0, b1, c0v, c1v;
            lds_v2u64(msm + (4 * i + q) * 4, a0, a1);
            lds_v2u64(msm + 64 + (4 * i + q) * 4, b0, b1);
            lds_v2u64(msm + 128 + (4 * i + q) * 4, c0v, c1v);
            u64 wa0 = W.w0[2 * i], wa1 = W.w0[2 * i + 1];
            u64 wb0 = W.w0[8 + 2 * i], wb1 = W.w0[8 + 2 * i + 1];
            d00 = ffma2(wa0, a0, d00);  d00 = ffma2(wa1, a1, d00);
            d01 = ffma2(wa0, b0, d01);  d01 = ffma2(wa1, b1, d01);
            d02 = ffma2(wa0, c0v, d02); d02 = ffma2(wa1, c1v, d02);
            d10 = ffma2(wb0, a0, d10);  d10 = ffma2(wb1, a1, d10);
            d11 = ffma2(wb0, b0, d11);  d11 = ffma2(wb1, b1, d11);
            d12 = ffma2(wb0, c0v, d12); d12 = ffma2(wb1, c1v, d12);
        }
        float k0 = qred_routed(hadd2(d00), hadd2(d10), par);
        float k1 = qred_routed(hadd2(d01), hadd2(d11), par);
        float k2 = qred_routed(hadd2(d02), hadd2(d12), par);
        if (q < 2) {
            int base = r + q * 64;
            tn0[base]       = g0p * k0;
            tn0[128 + base] = g0p * k1;
            tn0[256 + base] = g0p * k2;
        }
    }
    __syncthreads();
    // ---------- JVP layer 1 (K=128) ----------
    {
        u64 d00 = 0ull, d01 = 0ull, d02 = 0ull;
        u64 d10 = 0ull, d11 = 0ull, d12 = 0ull;
#pragma unroll
        for (int i = 0; i < 8; i++) {
            u64 a0, a1, b0, b1, c0v, c1v;
            lds_v2u64(tn0 + (4 * i + q) * 4, a0, a1);
            lds_v2u64(tn0 + 128 + (4 * i + q) * 4, b0, b1);
            lds_v2u64(tn0 + 256 + (4 * i + q) * 4, c0v, c1v);
            u64 wa0 = W.w1[2 * i], wa1 = W.w1[2 * i + 1];
            u64 wb0 = W.w1[16 + 2 * i], wb1 = W.w1[16 + 2 * i + 1];
            d00 = ffma2(wa0, a0, d00);  d00 = ffma2(wa1, a1, d00);
            d01 = ffma2(wa0, b0, d01);  d01 = ffma2(wa1, b1, d01);
            d02 = ffma2(wa0, c0v, d02); d02 = ffma2(wa1, c1v, d02);
            d10 = ffma2(wb0, a0, d10);  d10 = ffma2(wb1, a1, d10);
            d11 = ffma2(wb0, b0, d11);  d11 = ffma2(wb1, b1, d11);
            d12 = ffma2(wb0, c0v, d12); d12 = ffma2(wb1, c1v, d12);
        }
        float k0 = qred_routed(hadd2(d00), hadd2(d10), par);
        float k1 = qred_routed(hadd2(d01), hadd2(d11), par);
        float k2 = qred_routed(hadd2(d02), hadd2(d12), par);
        if (q < 2) {
            int base = r + q * 64;
            tn1[base]       = g1p * k0;
            tn1[128 + base] = g1p * k1;
            tn1[256 + base] = g1p * k2;
        }
    }
    __syncthreads();
    // ---------- JVP layer 2 — only the 6 J-blocks the bracket uses ----------
    // All-lane qreds here: the 6 terms must meet in one lane for the bracket.
    {
        u64 d01 = 0ull, d02 = 0ull;    // row r       x tangents 1,2
        u64 d10 = 0ull, d12 = 0ull;    // row r+64    x tangents 0,2
        u64 d20 = 0ull, d21 = 0ull;    // row 128+r   x tangents 0,1
#pragma unroll
        for (int i = 0; i < 8; i++) {
            u64 a0, a1, b0, b1, c0v, c1v;
            lds_v2u64(tn1 + (4 * i + q) * 4, a0, a1);
            lds_v2u64(tn1 + 128 + (4 * i + q) * 4, b0, b1);
            lds_v2u64(tn1 + 256 + (4 * i + q) * 4, c0v, c1v);
            u64 wa0 = W.w2a[2 * i], wa1 = W.w2a[2 * i + 1];
            u64 wb0 = W.w2a[16 + 2 * i], wb1 = W.w2a[16 + 2 * i + 1];
            u64 wc0 = W.w2b[2 * i], wc1 = W.w2b[2 * i + 1];
            d01 = ffma2(wa0, b0, d01);  d01 = ffma2(wa1, b1, d01);
            d02 = ffma2(wa0, c0v, d02); d02 = ffma2(wa1, c1v, d02);
            d10 = ffma2(wb0, a0, d10);  d10 = ffma2(wb1, a1, d10);
            d12 = ffma2(wb0, c0v, d12); d12 = ffma2(wb1, c1v, d12);
            d20 = ffma2(wc0, a0, d20);  d20 = ffma2(wc1, a1, d20);
            d21 = ffma2(wc0, b0, d21);  d21 = ffma2(wc1, b1, d21);
        }
        float e01 = qred(hadd2(d01)), e02 = qred(hadd2(d02));
        float e10 = qred(hadd2(d10)), e12 = qred(hadd2(d12));
        float e20 = qred(hadd2(d20)), e21 = qred(hadd2(d21));
        // gather row-(r+64) tanh state onto even lanes
        float mb_  = __shfl_xor_sync(0xffffffffu, m_ab, 1);
        float tzb_ = __shfl_xor_sync(0xffffffffu, tz_ab, 1);
        // valid on EVEN lanes: m_ab=ma, tz_ab=tza, mb_=mb, tzb_=tzb
        float br01 = tzb_ * e10 - tz_ab * e01;
        float br02 = tzc  * e20 - tz_ab * e02;
        float br12 = tzc  * e21 - tzb_ * e12;
        float k =  m_ab * svec[0] + mb_ * svec[1] + mc * svec[2]
                 + br01 * svec[3] + br02 * svec[4] + br12 * svec[5];
        return k;   // valid on even lanes; caller predicates on q==0
    }
}

// Output projection: out_row[o] = tanh(dot(y, R[o,:]) + rb[o])
// 256 threads: 8 threads per output, 8-dim partials, shuffle-reduce.
__device__ __forceinline__ void write_out_row(const float* sm, int t, float* __restrict__ dst)
{
    int o = t >> 3, part = t & 7;
    const float* r = sm + OFF_R + o * 64 + part * 8;
    const float* y = sm + OFF_Y + part * 8;
    float s = 0.f;
#pragma unroll
    for (int j = 0; j < 8; j++) s = fmaf(r[j], y[j], s);
    s += __shfl_xor_sync(0xffffffffu, s, 1);
    s += __shfl_xor_sync(0xffffffffu, s, 2);
    s += __shfl_xor_sync(0xffffffffu, s, 4);
    if (part == 0) dst[o] = ftanh(s + sm[OFF_RB + o]);
}

__global__ void __launch_bounds__(NTHREADS, 1)
ncde_kernel(const float* __restrict__ ts, const float* __restrict__ x,
            const float* __restrict__ W0, const float* __restrict__ b0,
            const float* __restrict__ W1, const float* __restrict__ b1,
            const float* __restrict__ W2, const float* __restrict__ b2,
            const float* __restrict__ V0, const float* __restrict__ c0,
            const float* __restrict__ V1, const float* __restrict__ c1,
            const float* __restrict__ V2, const float* __restrict__ c2,
            const float* __restrict__ R,  const float* __restrict__ rb,
            float* __restrict__ out)
{
    extern __shared__ float sm[];
    const int t = threadIdx.x;
    const int b = blockIdx.x;
    const int r = t >> 2, q = t & 3;

    // ---- pin per-thread weight slices in registers (packed f32x2) ----
    FState W;
#pragma unroll
    for (int ro = 0; ro < 2; ro++) {
        int row = r + 64 * ro;
#pragma unroll
        for (int i = 0; i < 4; i++) {
            ulonglong2 v = *(const ulonglong2*)(V0 + row * 64 + (4 * i + q) * 4);
            W.w0[ro * 8 + 2 * i] = v.x; W.w0[ro * 8 + 2 * i + 1] = v.y;
        }
#pragma unroll
        for (int i = 0; i < 8; i++) {
            ulonglong2 v = *(const ulonglong2*)(V1 + row * 128 + (4 * i + q) * 4);
            W.w1[ro * 16 + 2 * i] = v.x; W.w1[ro * 16 + 2 * i + 1] = v.y;
        }
#pragma unroll
        for (int i = 0; i < 8; i++) {
            ulonglong2 v = *(const ulonglong2*)(V2 + row * 128 + (4 * i + q) * 4);
            W.w2a[ro * 16 + 2 * i] = v.x; W.w2a[ro * 16 + 2 * i + 1] = v.y;
        }
    }
#pragma unroll
    for (int i = 0; i < 8; i++) {
        ulonglong2 v = *(const ulonglong2*)(V2 + (128 + r) * 128 + (4 * i + q) * 4);
        W.w2b[2 * i] = v.x; W.w2b[2 * i + 1] = v.y;
    }

    // ---- stage small constants into SMEM ----
    for (int i = t; i < 2048; i += NTHREADS) sm[OFF_R + i] = R[i];
    if (t < 32) sm[OFF_RB + t] = rb[t];
    if (t < 128) { sm[OFF_C0 + t] = c0[t]; sm[OFF_C1 + t] = c1[t]; }
    if (t < 192) sm[OFF_C2 + t] = c2[t];

    // ---- per-batch: dt array ----
    {
        const float* tsb = ts + b * TLEN;
        for (int i = t; i < NSTEP; i += NTHREADS) sm[OFF_DTS + i] = tsb[i + 1] - tsb[i];
    }

    // ---- per-batch: window log-signature slopes (16 windows x 6 channels) ----
    if (t < NWIN) {
        const float* xp = x + (b * TLEN + t * 8) * 3;
        float p[9][3];
#pragma unroll
        for (int k = 0; k < 9; k++) {
            p[k][0] = xp[k * 3 + 0];
            p[k][1] = xp[k * 3 + 1];
            p[k][2] = xp[k * 3 + 2];
        }
        float a01 = 0.f, a10 = 0.f, a02 = 0.f, a20 = 0.f, a12 = 0.f, a21 = 0.f;
#pragma unroll
        for (int k = 0; k < 8; k++) {
            float r0 = p[k][0] - p[0][0], r1 = p[k][1] - p[0][1], r2 = p[k][2] - p[0][2];
            float d0 = p[k + 1][0] - p[k][0], d1 = p[k + 1][1] - p[k][1], d2 = p[k + 1][2] - p[k][2];
            a01 = fmaf(r0, d1, a01); a10 = fmaf(r1, d0, a10);
            a02 = fmaf(r0, d2, a02); a20 = fmaf(r2, d0, a20);
            a12 = fmaf(r1, d2, a12); a21 = fmaf(r2, d1, a21);
        }
        const float* tsb = ts + b * TLEN;
        float td = tsb[(t + 1) * 8] - tsb[t * 8];
        float* sl = sm + OFF_SLP + t * 8;
        sl[0] = (p[8][0] - p[0][0]) / td;
        sl[1] = (p[8][1] - p[0][1]) / td;
        sl[2] = (p[8][2] - p[0][2]) / td;
        sl[3] = (0.5f * (a01 - a10)) / td;
        sl[4] = (0.5f * (a02 - a20)) / td;
        sl[5] = (0.5f * (a12 - a21)) / td;
    }
    __syncthreads();

    // ---- init MLP: h0 = W2 @ sp(W1 @ sp(W0 @ x0 + b0) + b1) + b2 ----
    if (t < 128) {
        const float* xp = x + b * TLEN * 3;
        float x0 = xp[0], x1 = xp[1], x2 = xp[2];
        float u = b0[t] + W0[t * 3] * x0 + W0[t * 3 + 1] * x1 + W0[t * 3 + 2] * x2;
        float sp, gdummy;
        sp_sig(u, sp, gdummy);
        sm[OFF_S0 + t] = sp;
    }
    __syncthreads();
    if (t < 128) {
        float acc = b1[t];
        const float* w = W1 + t * 128;
#pragma unroll 4
        for (int j = 0; j < 128; j++) acc = fmaf(w[j], sm[OFF_S0 + j], acc);
        float sp, gdummy;
        sp_sig(acc, sp, gdummy);
        sm[OFF_S1 + t] = sp;
    }
    __syncthreads();
    if (t < 64) {
        float acc = b2[t];
        const float* w = W2 + t * 128;
#pragma unroll 4
        for (int j = 0; j < 128; j++) acc = fmaf(w[j], sm[OFF_S1 + j], acc);
        sm[OFF_Y + t] = acc;
    }
    __syncthreads();

    // ---- output row 0 (from h0) ----
    write_out_row(sm, t, out + (b * TLEN + 0) * OUTN);

    // ---- RK2 (Heun) scan over 128 steps ----
    for (int i = 0; i < NSTEP; i++) {
        float dt = sm[OFF_DTS + i];
        const float* svec = sm + OFF_SLP + ((i >> 3) << 3);

        float k1 = eval_F(sm, t, sm + OFF_Y, svec, W);
        if (q == 0) sm[OFF_Y2 + r] = sm[OFF_Y + r] + dt * k1;
        __syncthreads();

        float k2 = eval_F(sm, t, sm + OFF_Y2, svec, W);
        if (q == 0) sm[OFF_Y + r] = sm[OFF_Y + r] + 0.5f * dt * (k1 + k2);
        __syncthreads();

        write_out_row(sm, t, out + (b * TLEN + i + 1) * OUTN);
    }
}

extern "C" void kernel_launch(void* const* d_in, const int* in_sizes, int n_in,
                              void* d_out, int out_size)
{
    const float* ts = (const float*)d_in[0];
    const float* x  = (const float*)d_in[1];
    const float* W0 = (const float*)d_in[2];
    const float* b0 = (const float*)d_in[3];
    const float* W1 = (const float*)d_in[4];
    const float* b1 = (const float*)d_in[5];
    const float* W2 = (const float*)d_in[6];
    const float* b2 = (const float*)d_in[7];
    const float* V0 = (const float*)d_in[8];
    const float* c0 = (const float*)d_in[9];
    const float* V1 = (const float*)d_in[10];
    const float* c1 = (const float*)d_in[11];
    const float* V2 = (const float*)d_in[12];
    const float* c2 = (const float*)d_in[13];
    const float* R  = (const float*)d_in[14];
    const float* rb = (const float*)d_in[15];
    float* out = (float*)d_out;

    cudaFuncSetAttribute(ncde_kernel, cudaFuncAttributeMaxDynamicSharedMemorySize, SMEM_BYTES);
    ncde_kernel<<<BATCH, NTHREADS, SMEM_BYTES>>>(ts, x, W0, b0, W1, b1, W2, b2,
                                                 V0, c0, V1, c1, V2, c2, R, rb, out);
}

// round 14
// speedup vs baseline: 2.1750x; 1.0001x over previous
#include <cuda_runtime.h>
#include <math.h>

// Problem constants
#define NTHREADS 256
#define BATCH    128
#define TLEN     129
#define NSTEP    128   // TLEN-1
#define NWIN     16    // (TLEN-1)/8
#define OUTN     32

// ---- shared memory layout (float offsets) ----
// ALL weights live in per-thread registers (packed f32x2).
// Thread t = 4r+q (r<64,q<4) owns rows {r, r+64} of V0/V1/V2[0:128],
// row 128+r of V2[128:192], K-quarter q (float4 indices 4i+q).
#define OFF_R    0        // 2048  (R row-major 32x64)
#define OFF_RB   2048     // 32
#define OFF_C0   2080     // 128
#define OFF_C1   2208     // 128
#define OFF_C2   2336     // 192
#define OFF_Y    2528     // 64
#define OFF_Y2   2592     // 64
#define OFF_S0   2656     // 128
#define OFF_S1   2784     // 128
#define OFF_M    2912     // 192
#define OFF_TN0  3104     // 3*128
#define OFF_TN1  3488     // 3*128
#define OFF_SLP  3872     // 16*8 (6 used per window)
#define OFF_DTS  4000     // 128
#define SMEM_FLOATS 4128
#define SMEM_BYTES  (SMEM_FLOATS * 4)

typedef unsigned long long u64;

// ---- fast transcendentals (MUFU-based; rel err ~1e-7, budget is 1e-3) ----
__device__ __forceinline__ float frcp_(float x) {
    float r;
    asm("rcp.approx.ftz.f32 %0, %1;" : "=f"(r) : "f"(x));
    return r;
}
// softplus + sigmoid sharing one exp:
//   e = exp(-|u|); sp = max(u,0)+log(1+e); sig = u>0 ? 1/(1+e) : e/(1+e)
__device__ __forceinline__ void sp_sig(float u, float& sp, float& g) {
    float e = __expf(-fabsf(u));
    float den = frcp_(1.0f + e);
    sp = fmaxf(u, 0.0f) + __logf(1.0f + e);
    g = (u > 0.0f) ? den : e * den;
}
// tanh + (1-tanh^2):  m = 1 - 2/(1+exp(2z))  (overflow -> inf -> rcp=0 -> m=1)
__device__ __forceinline__ void tanh_tz(float z, float& m, float& tz) {
    float e2 = __expf(2.0f * z);
    float w = frcp_(1.0f + e2);
    m = fmaf(-2.0f, w, 1.0f);
    tz = 1.0f - m * m;
}
__device__ __forceinline__ float ftanh(float z) {
    float e2 = __expf(2.0f * z);
    return fmaf(-2.0f, frcp_(1.0f + e2), 1.0f);
}

// packed f32x2 fma: lanewise d = a*b + c
__device__ __forceinline__ u64 ffma2(u64 a, u64 b, u64 c) {
    u64 d;
    asm("fma.rn.f32x2 %0, %1, %2, %3;" : "=l"(d) : "l"(a), "l"(b), "l"(c));
    return d;
}
// horizontal add of the two f32 lanes
__device__ __forceinline__ float hadd2(u64 v) {
    unsigned lo, hi;
    asm("mov.b64 {%0, %1}, %2;" : "=r"(lo), "=r"(hi) : "l"(v));
    return __uint_as_float(lo) + __uint_as_float(hi);
}
// LDS.128 into two packed f32x2 (64-bit register pairs)
__device__ __forceinline__ void lds_v2u64(const float* p, u64& a, u64& b) {
    unsigned addr = (unsigned)__cvta_generic_to_shared(p);
    asm volatile("ld.shared.v2.u64 {%0, %1}, [%2];" : "=l"(a), "=l"(b) : "r"(addr));
}
// standard butterfly reduce over 4 consecutive lanes (result valid in ALL lanes)
__device__ __forceinline__ float qred(float s) {
    s += __shfl_xor_sync(0xffffffffu, s, 1);
    s += __shfl_xor_sync(0xffffffffu, s, 2);
    return s;
}
// value-routed quad reduce of a row-pair (ea: row A partial, eb: row B partial).
// Returns my-parity row's FULL quad sum: even lanes -> sum(ea), odd -> sum(eb).
// Tree is (q0+q1)+(q2+q3), identical to qred.
__device__ __forceinline__ float qred_routed(float ea, float eb, int par) {
    float send = par ? ea : eb;
    float recv = __shfl_xor_sync(0xffffffffu, send, 1);
    float kept = (par ? eb : ea) + recv;
    kept += __shfl_xor_sync(0xffffffffu, kept, 2);
    return kept;
}

// Persistent per-thread register-resident weights
struct FState {
    u64 w0[16];   // V0 rows r,r+64   : [row01*8  + 2i + j], i<4
    u64 w1[32];   // V1 rows r,r+64   : [row01*16 + 2i + j], i<8
    u64 w2a[32];  // V2 rows r,r+64   : [row01*16 + 2i + j], i<8
    u64 w2b[16];  // V2 row 128+r     : [2i + j], i<8
};

// F(y) . s. 256 threads, row-pair x quarter-K split, all weights in registers.
// Parity-routed reductions: even lanes carry row r, odd lanes row r+64.
// Returns k[r] valid on EVEN lanes (caller uses q==0).
// NO trailing barrier — caller must __syncthreads() after consuming k.
__device__ __forceinline__ float eval_F(float* sm, int tid,
                                        const float* __restrict__ yin,
                                        const float* __restrict__ svec,
                                        const FState& W)
{
    const int r = tid >> 2, q = tid & 3;
    const int par = q & 1;                   // 0: row r, 1: row r+64
    const int rowoff = par ? 64 : 0;
    float* s0  = sm + OFF_S0;
    float* s1  = sm + OFF_S1;
    float* msm = sm + OFF_M;
    float* tn0 = sm + OFF_TN0;
    float* tn1 = sm + OFF_TN1;

    float g0p, g1p;            // sigmoid gates for my parity row
    float m_ab, tz_ab;         // tanh for my parity row
    float mc, tzc;             // tanh row 128+r (all lanes)

    // ---------- forward layer 0: u0 = V0 @ y + c0 (K=64) ----------
    {
        u64 acc0 = 0ull, acc1 = 0ull;
#pragma unroll
        for (int i = 0; i < 4; i++) {
            u64 a0, a1;
            lds_v2u64(yin + (4 * i + q) * 4, a0, a1);
            acc0 = ffma2(W.w0[2 * i], a0, acc0);
            acc0 = ffma2(W.w0[2 * i + 1], a1, acc0);
            acc1 = ffma2(W.w0[8 + 2 * i], a0, acc1);
            acc1 = ffma2(W.w0[8 + 2 * i + 1], a1, acc1);
        }
        float kept = qred_routed(hadd2(acc0), hadd2(acc1), par);
        float u = sm[OFF_C0 + r + rowoff] + kept;
        float sp;
        sp_sig(u, sp, g0p);
        if (q < 2) s0[r + q * 64] = sp;
    }
    __syncthreads();
    // ---------- forward layer 1 (K=128) ----------
    {
        u64 acc0 = 0ull, acc1 = 0ull;
#pragma unroll
        for (int i = 0; i < 8; i++) {
            u64 a0, a1;
            lds_v2u64(s0 + (4 * i + q) * 4, a0, a1);
            acc0 = ffma2(W.w1[2 * i], a0, acc0);
            acc0 = ffma2(W.w1[2 * i + 1], a1, acc0);
            acc1 = ffma2(W.w1[16 + 2 * i], a0, acc1);
            acc1 = ffma2(W.w1[16 + 2 * i + 1], a1, acc1);
        }
        float kept = qred_routed(hadd2(acc0), hadd2(acc1), par);
        float u = sm[OFF_C1 + r + rowoff] + kept;
        float sp;
        sp_sig(u, sp, g1p);
        if (q < 2) s1[r + q * 64] = sp;
    }
    __syncthreads();
    // ---------- forward layer 2 (192 rows: r/r+64 routed, 128+r all-lane) ----------
    {
        u64 acc0 = 0ull, acc1 = 0ull, acc2 = 0ull;
#pragma unroll
        for (int i = 0; i < 8; i++) {
            u64 a0, a1;
            lds_v2u64(s1 + (4 * i + q) * 4, a0, a1);
            acc0 = ffma2(W.w2a[2 * i], a0, acc0);
            acc0 = ffma2(W.w2a[2 * i + 1], a1, acc0);
            acc1 = ffma2(W.w2a[16 + 2 * i], a0, acc1);
            acc1 = ffma2(W.w2a[16 + 2 * i + 1], a1, acc1);
            acc2 = ffma2(W.w2b[2 * i], a0, acc2);
            acc2 = ffma2(W.w2b[2 * i + 1], a1, acc2);
        }
        float kab = qred_routed(hadd2(acc0), hadd2(acc1), par);
        float sc  = qred(hadd2(acc2));
        tanh_tz(sm[OFF_C2 + r + rowoff] + kab, m_ab, tz_ab);
        tanh_tz(sm[OFF_C2 + 128 + r] + sc, mc, tzc);
        if (q < 2) msm[r + q * 64] = m_ab;
        if (q == 0) msm[128 + r] = mc;
    }
    __syncthreads();
    // ---------- JVP layer 0 (3 tangents = rows of m; K=64) ----------
    {
        u64 d00 = 0ull, d01 = 0ull, d02 = 0ull;
        u64 d10 = 0ull, d11 = 0ull, d12 = 0ull;
#pragma unroll
        for (int i = 0; i < 4; i++) {
            u64 a0, a1, b0, b1, c0v, c1v;
            lds_v2u64(msm + (4 * i + q) * 4, a0, a1);
            lds_v2u64(msm + 64 + (4 * i + q) * 4, b0, b1);
            lds_v2u64(msm + 128 + (4 * i + q) * 4, c0v, c1v);
            u64 wa0 = W.w0[2 * i], wa1 = W.w0[2 * i + 1];
            u64 wb0 = W.w0[8 + 2 * i], wb1 = W.w0[8 + 2 * i + 1];
            d00 = ffma2(wa0, a0, d00);  d00 = ffma2(wa1, a1, d00);
            d01 = ffma2(wa0, b0, d01);  d01 = ffma2(wa1, b1, d01);
            d02 = ffma2(wa0, c0v, d02); d02 = ffma2(wa1, c1v, d02);
            d10 = ffma2(wb0, a0, d10);  d10 = ffma2(wb1, a1, d10);
            d11 = ffma2(wb0, b0, d11);  d11 = ffma2(wb1, b1, d11);
            d12 = ffma2(wb0, c0v, d12); d12 = ffma2(wb1, c1v, d12);
        }
        float k0 = qred_routed(hadd2(d00), hadd2(d10), par);
        float k1 = qred_routed(hadd2(d01), hadd2(d11), par);
        float k2 = qred_routed(hadd2(d02), hadd2(d12), par);
        if (q < 2) {
            int base = r + q * 64;
            tn0[base]       = g0p * k0;
            tn0[128 + base] = g0p * k1;
            tn0[256 + base] = g0p * k2;
        }
    }
    __syncthreads();
    // ---------- JVP layer 1 (K=128) ----------
    {
        u64 d00 = 0ull, d01 = 0ull, d02 = 0ull;
        u64 d10 = 0ull, d11 = 0ull, d12 = 0ull;
#pragma unroll
        for (int i = 0; i < 8; i++) {
            u64 a0, a1, b0, b1, c0v, c1v;
            lds_v2u64(tn0 + (4 * i + q) * 4, a0, a1);
            lds_v2u64(tn0 + 128 + (4 * i + q) * 4, b0, b1);
            lds_v2u64(tn0 + 256 + (4 * i + q) * 4, c0v, c1v);
            u64 wa0 = W.w1[2 * i], wa1 = W.w1[2 * i + 1];
            u64 wb0 = W.w1[16 + 2 * i], wb1 = W.w1[16 + 2 * i + 1];
            d00 = ffma2(wa0, a0, d00);  d00 = ffma2(wa1, a1, d00);
            d01 = ffma2(wa0, b0, d01);  d01 = ffma2(wa1, b1, d01);
            d02 = ffma2(wa0, c0v, d02); d02 = ffma2(wa1, c1v, d02);
            d10 = ffma2(wb0, a0, d10);  d10 = ffma2(wb1, a1, d10);
            d11 = ffma2(wb0, b0, d11);  d11 = ffma2(wb1, b1, d11);
            d12 = ffma2(wb0, c0v, d12); d12 = ffma2(wb1, c1v, d12);
        }
        float k0 = qred_routed(hadd2(d00), hadd2(d10), par);
        float k1 = qred_routed(hadd2(d01), hadd2(d11), par);
        float k2 = qred_routed(hadd2(d02), hadd2(d12), par);
        if (q < 2) {
            int base = r + q * 64;
            tn1[base]       = g1p * k0;
            tn1[128 + base] = g1p * k1;
            tn1[256 + base] = g1p * k2;
        }
    }
    __syncthreads();
    // ---------- JVP layer 2 — only the 6 J-blocks the bracket uses ----------
    // All-lane qreds here: the 6 terms must meet in one lane for the bracket.
    {
        u64 d01 = 0ull, d02 = 0ull;    // row r       x tangents 1,2
        u64 d10 = 0ull, d12 = 0ull;    // row r+64    x tangents 0,2
        u64 d20 = 0ull, d21 = 0ull;    // row 128+r   x tangents 0,1
#pragma unroll
        for (int i = 0; i < 8; i++) {
            u64 a0, a1, b0, b1, c0v, c1v;
            lds_v2u64(tn1 + (4 * i + q) * 4, a0, a1);
            lds_v2u64(tn1 + 128 + (4 * i + q) * 4, b0, b1);
            lds_v2u64(tn1 + 256 + (4 * i + q) * 4, c0v, c1v);
            u64 wa0 = W.w2a[2 * i], wa1 = W.w2a[2 * i + 1];
            u64 wb0 = W.w2a[16 + 2 * i], wb1 = W.w2a[16 + 2 * i + 1];
            u64 wc0 = W.w2b[2 * i], wc1 = W.w2b[2 * i + 1];
            d01 = ffma2(wa0, b0, d01);  d01 = ffma2(wa1, b1, d01);
            d02 = ffma2(wa0, c0v, d02); d02 = ffma2(wa1, c1v, d02);
            d10 = ffma2(wb0, a0, d10);  d10 = ffma2(wb1, a1, d10);
            d12 = ffma2(wb0, c0v, d12); d12 = ffma2(wb1, c1v, d12);
            d20 = ffma2(wc0, a0, d20);  d20 = ffma2(wc1, a1, d20);
            d21 = ffma2(wc0, b0, d21);  d21 = ffma2(wc1, b1, d21);
        }
        float e01 = qred(hadd2(d01)), e02 = qred(hadd2(d02));
        float e10 = qred(hadd2(d10)), e12 = qred(hadd2(d12));
        float e20 = qred(hadd2(d20)), e21 = qred(hadd2(d21));
        // gather row-(r+64) tanh state onto even lanes
        float mb_  = __shfl_xor_sync(0xffffffffu, m_ab, 1);
        float tzb_ = __shfl_xor_sync(0xffffffffu, tz_ab, 1);
        // valid on EVEN lanes: m_ab=ma, tz_ab=tza, mb_=mb, tzb_=tzb
        float br01 = tzb_ * e10 - tz_ab * e01;
        float br02 = tzc  * e20 - tz_ab * e02;
        float br12 = tzc  * e21 - tzb_ * e12;
        float k =  m_ab * svec[0] + mb_ * svec[1] + mc * svec[2]
                 + br01 * svec[3] + br02 * svec[4] + br12 * svec[5];
        return k;   // valid on even lanes; caller predicates on q==0
    }
}

// Output projection: out_row[o] = tanh(dot(y, R[o,:]) + rb[o])
// 256 threads: 8 threads per output, 8-dim partials, shuffle-reduce.
__device__ __forceinline__ void write_out_row(const float* sm, int t, float* __restrict__ dst)
{
    int o = t >> 3, part = t & 7;
    const float* r = sm + OFF_R + o * 64 + part * 8;
    const float* y = sm + OFF_Y + part * 8;
    float s = 0.f;
#pragma unroll
    for (int j = 0; j < 8; j++) s = fmaf(r[j], y[j], s);
    s += __shfl_xor_sync(0xffffffffu, s, 1);
    s += __shfl_xor_sync(0xffffffffu, s, 2);
    s += __shfl_xor_sync(0xffffffffu, s, 4);
    if (part == 0) dst[o] = ftanh(s + sm[OFF_RB + o]);
}

__global__ void __launch_bounds__(NTHREADS, 1)
ncde_kernel(const float* __restrict__ ts, const float* __restrict__ x,
            const float* __restrict__ W0, const float* __restrict__ b0,
            const float* __restrict__ W1, const float* __restrict__ b1,
            const float* __restrict__ W2, const float* __restrict__ b2,
            const float* __restrict__ V0, const float* __restrict__ c0,
            const float* __restrict__ V1, const float* __restrict__ c1,
            const float* __restrict__ V2, const float* __restrict__ c2,
            const float* __restrict__ R,  const float* __restrict__ rb,
            float* __restrict__ out)
{
    extern __shared__ float sm[];
    const int t = threadIdx.x;
    const int b = blockIdx.x;
    const int r = t >> 2, q = t & 3;

    // ---- pin per-thread weight slices in registers (packed f32x2) ----
    FState W;
#pragma unroll
    for (int ro = 0; ro < 2; ro++) {
        int row = r + 64 * ro;
#pragma unroll
        for (int i = 0; i < 4; i++) {
            ulonglong2 v = *(const ulonglong2*)(V0 + row * 64 + (4 * i + q) * 4);
            W.w0[ro * 8 + 2 * i] = v.x; W.w0[ro * 8 + 2 * i + 1] = v.y;
        }
#pragma unroll
        for (int i = 0; i < 8; i++) {
            ulonglong2 v = *(const ulonglong2*)(V1 + row * 128 + (4 * i + q) * 4);
            W.w1[ro * 16 + 2 * i] = v.x; W.w1[ro * 16 + 2 * i + 1] = v.y;
        }
#pragma unroll
        for (int i = 0; i < 8; i++) {
            ulonglong2 v = *(const ulonglong2*)(V2 + row * 128 + (4 * i + q) * 4);
            W.w2a[ro * 16 + 2 * i] = v.x; W.w2a[ro * 16 + 2 * i + 1] = v.y;
        }
    }
#pragma unroll
    for (int i = 0; i < 8; i++) {
        ulonglong2 v = *(const ulonglong2*)(V2 + (128 + r) * 128 + (4 * i + q) * 4);
        W.w2b[2 * i] = v.x; W.w2b[2 * i + 1] = v.y;
    }

    // ---- stage small constants into SMEM ----
    for (int i = t; i < 2048; i += NTHREADS) sm[OFF_R + i] = R[i];
    if (t < 32) sm[OFF_RB + t] = rb[t];
    if (t < 128) { sm[OFF_C0 + t] = c0[t]; sm[OFF_C1 + t] = c1[t]; }
    if (t < 192) sm[OFF_C2 + t] = c2[t];

    // ---- per-batch: dt array ----
    {
        const float* tsb = ts + b * TLEN;
        for (int i = t; i < NSTEP; i += NTHREADS) sm[OFF_DTS + i] = tsb[i + 1] - tsb[i];
    }

    // ---- per-batch: window log-signature slopes (16 windows x 6 channels) ----
    if (t < NWIN) {
        const float* xp = x + (b * TLEN + t * 8) * 3;
        float p[9][3];
#pragma unroll
        for (int k = 0; k < 9; k++) {
            p[k][0] = xp[k * 3 + 0];
            p[k][1] = xp[k * 3 + 1];
            p[k][2] = xp[k * 3 + 2];
        }
        float a01 = 0.f, a10 = 0.f, a02 = 0.f, a20 = 0.f, a12 = 0.f, a21 = 0.f;
#pragma unroll
        for (int k = 0; k < 8; k++) {
            float r0 = p[k][0] - p[0][0], r1 = p[k][1] - p[0][1], r2 = p[k][2] - p[0][2];
            float d0 = p[k + 1][0] - p[k][0], d1 = p[k + 1][1] - p[k][1], d2 = p[k + 1][2] - p[k][2];
            a01 = fmaf(r0, d1, a01); a10 = fmaf(r1, d0, a10);
            a02 = fmaf(r0, d2, a02); a20 = fmaf(r2, d0, a20);
            a12 = fmaf(r1, d2, a12); a21 = fmaf(r2, d1, a21);
        }
        const float* tsb = ts + b * TLEN;
        float td = tsb[(t + 1) * 8] - tsb[t * 8];
        float* sl = sm + OFF_SLP + t * 8;
        sl[0] = (p[8][0] - p[0][0]) / td;
        sl[1] = (p[8][1] - p[0][1]) / td;
        sl[2] = (p[8][2] - p[0][2]) / td;
        sl[3] = (0.5f * (a01 - a10)) / td;
        sl[4] = (0.5f * (a02 - a20)) / td;
        sl[5] = (0.5f * (a12 - a21)) / td;
    }
    __syncthreads();

    // ---- init MLP: h0 = W2 @ sp(W1 @ sp(W0 @ x0 + b0) + b1) + b2 ----
    if (t < 128) {
        const float* xp = x + b * TLEN * 3;
        float x0 = xp[0], x1 = xp[1], x2 = xp[2];
        float u = b0[t] + W0[t * 3] * x0 + W0[t * 3 + 1] * x1 + W0[t * 3 + 2] * x2;
        float sp, gdummy;
        sp_sig(u, sp, gdummy);
        sm[OFF_S0 + t] = sp;
    }
    __syncthreads();
    if (t < 128) {
        float acc = b1[t];
        const float* w = W1 + t * 128;
#pragma unroll 4
        for (int j = 0; j < 128; j++) acc = fmaf(w[j], sm[OFF_S0 + j], acc);
        float sp, gdummy;
        sp_sig(acc, sp, gdummy);
        sm[OFF_S1 + t] = sp;
    }
    __syncthreads();
    if (t < 64) {
        float acc = b2[t];
        const float* w = W2 + t * 128;
#pragma unroll 4
        for (int j = 0; j < 128; j++) acc = fmaf(w[j], sm[OFF_S1 + j], acc);
        sm[OFF_Y + t] = acc;
    }
    __syncthreads();

    // ---- output row 0 (from h0) ----
    write_out_row(sm, t, out + (b * TLEN + 0) * OUTN);

    // ---- RK2 (Heun) scan over 128 steps ----
    for (int i = 0; i < NSTEP; i++) {
        float dt = sm[OFF_DTS + i];
        const float* svec = sm + OFF_SLP + ((i >> 3) << 3);

        float k1 = eval_F(sm, t, sm + OFF_Y, svec, W);
        if (q == 0) sm[OFF_Y2 + r] = sm[OFF_Y + r] + dt * k1;
        __syncthreads();

        float k2 = eval_F(sm, t, sm + OFF_Y2, svec, W);
        if (q == 0) sm[OFF_Y + r] = sm[OFF_Y + r] + 0.5f * dt * (k1 + k2);
        __syncthreads();

        write_out_row(sm, t, out + (b * TLEN + i + 1) * OUTN);
    }
}

extern "C" void kernel_launch(void* const* d_in, const int* in_sizes, int n_in,
                              void* d_out, int out_size)
{
    const float* ts = (const float*)d_in[0];
    const float* x  = (const float*)d_in[1];
    const float* W0 = (const float*)d_in[2];
    const float* b0 = (const float*)d_in[3];
    const float* W1 = (const float*)d_in[4];
    const float* b1 = (const float*)d_in[5];
    const float* W2 = (const float*)d_in[6];
    const float* b2 = (const float*)d_in[7];
    const float* V0 = (const float*)d_in[8];
    const float* c0 = (const float*)d_in[9];
    const float* V1 = (const float*)d_in[10];
    const float* c1 = (const float*)d_in[11];
    const float* V2 = (const float*)d_in[12];
    const float* c2 = (const float*)d_in[13];
    const float* R  = (const float*)d_in[14];
    const float* rb = (const float*)d_in[15];
    float* out = (float*)d_out;

    cudaFuncSetAttribute(ncde_kernel, cudaFuncAttributeMaxDynamicSharedMemorySize, SMEM_BYTES);
    ncde_kernel<<<BATCH, NTHREADS, SMEM_BYTES>>>(ts, x, W0, b0, W1, b1, W2, b2,
                                                 V0, c0, V1, c1, V2, c2, R, rb, out);
}